// round 10
// baseline (speedup 1.0000x reference)
#include <cuda_runtime.h>
#include <cuda_bf16.h>
#include <cstdint>

#define NN 100000
#define NPAD 100096   // 782*128, padded rows stay zero forever
#define NE 1600000
#define NG 1024
#define DD 128
#define NB_SCAN 391   // ceil(NN/256)

// ---------------- scratch (device globals; zero-initialized at load; every call
// re-zeros deg/cursor/pool/alloc in k_final's tail; plane pad rows never written)
__device__ float g_h1[NN * DD];
__device__ float g_h2[NN * DD];
__device__ __nv_bfloat16 g_xH[NPAD * DD];
__device__ __nv_bfloat16 g_xL[NPAD * DD];
__device__ __nv_bfloat16 g_aH[NPAD * DD];
__device__ __nv_bfloat16 g_aL[NPAD * DD];
__device__ __nv_bfloat16 g_hH[NPAD * DD];
__device__ __nv_bfloat16 g_hL[NPAD * DD];
__device__ float g_pool[NG * DD];
// W in fragment order: [layer][j(n-tile 0..15)][s(k-step 0..15)][lane 0..31] -> uint2
__device__ uint2 g_WfH[2 * 16 * 16 * 32];
__device__ uint2 g_WfL[2 * 16 * 16 * 32];
__device__ int   g_deg[NN];
__device__ int   g_rowptr[NN];      // allocated bucket start (NOT sorted prefix)
__device__ int   g_cursor[NN];
__device__ int   g_esrc[NE];
__device__ int   g_alloc;           // bump allocator for buckets

// ---------------- helpers ----------------
__device__ __forceinline__ uint32_t smem_to_u32(const void* p) {
    uint32_t a;
    asm("{ .reg .u64 t; cvta.to.shared.u64 t, %1; cvt.u32.u64 %0, t; }" : "=r"(a) : "l"(p));
    return a;
}
__device__ __forceinline__ uint32_t bf2u(__nv_bfloat162 v) { return *reinterpret_cast<uint32_t*>(&v); }

#define ADD_F32X2(d, a, b) \
    asm("add.rn.f32x2 %0, %1, %2;" : "=l"(d) : "l"(a), "l"(b))
#define UNPACK_F32X2(lo, hi, in) \
    asm("mov.b64 {%0, %1}, %2;" : "=f"(lo), "=f"(hi) : "l"(in))

#define LDM_X4(r, addr) \
    asm volatile("ldmatrix.sync.aligned.m8n8.x4.shared.b16 {%0,%1,%2,%3}, [%4];" \
        : "=r"((r)[0]), "=r"((r)[1]), "=r"((r)[2]), "=r"((r)[3]) : "r"(addr))

#define MMA_BF16(c, a, b) \
    asm volatile("mma.sync.aligned.m16n8k16.row.col.f32.bf16.bf16.f32 " \
        "{%0,%1,%2,%3}, {%4,%5,%6,%7}, {%8,%9}, {%0,%1,%2,%3};" \
        : "+f"((c)[0]), "+f"((c)[1]), "+f"((c)[2]), "+f"((c)[3]) \
        : "r"((a)[0]), "r"((a)[1]), "r"((a)[2]), "r"((a)[3]), "r"((b).x), "r"((b).y))

// ---------------- slot 0: prep (x->hi/lo planes, W frag split) + degree count --------
#define PREP_XB_BLKS 12500   // NN*DD/4 / 256
#define PREP_WF_BLKS 64
__global__ void k_prep_deg(const float* __restrict__ x,
                           const float* __restrict__ W1l, const float* __restrict__ W1r,
                           const float* __restrict__ W2l, const float* __restrict__ W2r,
                           const int* __restrict__ dst) {
    if (blockIdx.x < PREP_XB_BLKS) {
        int i = blockIdx.x * 256 + threadIdx.x;
        float4 f = ((const float4*)x)[i];
        __nv_bfloat162 h01 = __floats2bfloat162_rn(f.x, f.y);
        __nv_bfloat162 h23 = __floats2bfloat162_rn(f.z, f.w);
        __nv_bfloat162 l01 = __floats2bfloat162_rn(f.x - __bfloat162float(h01.x),
                                                   f.y - __bfloat162float(h01.y));
        __nv_bfloat162 l23 = __floats2bfloat162_rn(f.z - __bfloat162float(h23.x),
                                                   f.w - __bfloat162float(h23.y));
        ((uint2*)g_xH)[i] = make_uint2(bf2u(h01), bf2u(h23));
        ((uint2*)g_xL)[i] = make_uint2(bf2u(l01), bf2u(l23));
        return;
    }
    if (blockIdx.x < PREP_XB_BLKS + PREP_WF_BLKS) {
        int i = (blockIdx.x - PREP_XB_BLKS) * 256 + threadIdx.x;   // 0 .. 16383
        if (i >= 2 * 16 * 16 * 32) return;
        int lane = i & 31;
        int s = (i >> 5) & 15;
        int j = (i >> 9) & 15;
        int layer = i >> 13;
        int n = j * 8 + (lane >> 2);
        int k = s * 16 + (lane & 3) * 2;
        const float* Wl = layer ? W2l : W1l;
        const float* Wr = layer ? W2r : W1r;
        float w[4];
#pragma unroll
        for (int q = 0; q < 4; q++) {
            int kk = k + (q >> 1) * 8 + (q & 1);
            w[q] = (kk < DD) ? Wl[n * DD + kk] : Wr[n * DD + (kk - DD)];
        }
        __nv_bfloat16 h[4], l[4];
#pragma unroll
        for (int q = 0; q < 4; q++) {
            h[q] = __float2bfloat16(w[q]);
            l[q] = __float2bfloat16(w[q] - __bfloat162float(h[q]));
        }
        __nv_bfloat162 h01; h01.x = h[0]; h01.y = h[1];
        __nv_bfloat162 h23; h23.x = h[2]; h23.y = h[3];
        __nv_bfloat162 l01; l01.x = l[0]; l01.y = l[1];
        __nv_bfloat162 l23; l23.x = l[2]; l23.y = l[3];
        g_WfH[i] = make_uint2(bf2u(h01), bf2u(h23));
        g_WfL[i] = make_uint2(bf2u(l01), bf2u(l23));
        return;
    }
    int i = (blockIdx.x - PREP_XB_BLKS - PREP_WF_BLKS) * 256 + threadIdx.x;
    if (i < NE) atomicAdd(&g_deg[dst[i]], 1);
}

// ---------------- slot 1: bucket allocation (local scan + one atomic per block) ----
__global__ void k_alloc() {
    __shared__ int s[256];
    __shared__ int base;
    int b = blockIdx.x, t = threadIdx.x;
    int i = b * 256 + t;
    int v = (i < NN) ? g_deg[i] : 0;
    s[t] = v;
    __syncthreads();
#pragma unroll
    for (int off = 1; off < 256; off <<= 1) {
        int add = (t >= off) ? s[t - off] : 0;
        __syncthreads();
        s[t] += add;
        __syncthreads();
    }
    if (t == 255) base = atomicAdd(&g_alloc, s[255]);
    __syncthreads();
    if (i < NN) g_rowptr[i] = base + s[t] - v;
}

// ---------------- slot 2: scatter edges into buckets ----------------
__global__ void k_scatter(const int* __restrict__ src, const int* __restrict__ dst) {
    int i = blockIdx.x * blockDim.x + threadIdx.x;
    if (i >= NE) return;
    int d = dst[i];
    int pos = atomicAdd(&g_cursor[d], 1);
    g_esrc[g_rowptr[d] + pos] = src[i];
}

// ---------------- slot 3 (PROFILED): mean aggregation, warp per node ----------------
// fp32 gather (exact), packed f32x2 accumulate, emits bf16 hi/lo planes.
__global__ void k_agg(const float* __restrict__ in,
                      __nv_bfloat16* __restrict__ outH, __nv_bfloat16* __restrict__ outL) {
    int w = (blockIdx.x * blockDim.x + threadIdx.x) >> 5;
    int lane = threadIdx.x & 31;
    if (w >= NN) return;
    int beg = g_rowptr[w];
    int dcnt = g_deg[w];
    int end = beg + dcnt;
    const ulonglong2* in2 = (const ulonglong2*)in;   // 16B per lane-slot, 32 slots/row
    unsigned long long pa01 = 0ull, pa23 = 0ull, pb01 = 0ull, pb23 = 0ull;  // f32x2 zeros
    int e = beg;
#pragma unroll 1
    for (; e + 7 < end; e += 8) {
        int s0 = __ldg(&g_esrc[e]);
        int s1 = __ldg(&g_esrc[e + 1]);
        int s2 = __ldg(&g_esrc[e + 2]);
        int s3 = __ldg(&g_esrc[e + 3]);
        int s4 = __ldg(&g_esrc[e + 4]);
        int s5 = __ldg(&g_esrc[e + 5]);
        int s6 = __ldg(&g_esrc[e + 6]);
        int s7 = __ldg(&g_esrc[e + 7]);
        ulonglong2 v0 = in2[(size_t)s0 * 32 + lane];
        ulonglong2 v1 = in2[(size_t)s1 * 32 + lane];
        ulonglong2 v2 = in2[(size_t)s2 * 32 + lane];
        ulonglong2 v3 = in2[(size_t)s3 * 32 + lane];
        ulonglong2 v4 = in2[(size_t)s4 * 32 + lane];
        ulonglong2 v5 = in2[(size_t)s5 * 32 + lane];
        ulonglong2 v6 = in2[(size_t)s6 * 32 + lane];
        ulonglong2 v7 = in2[(size_t)s7 * 32 + lane];
        ADD_F32X2(pa01, pa01, v0.x); ADD_F32X2(pa23, pa23, v0.y);
        ADD_F32X2(pb01, pb01, v1.x); ADD_F32X2(pb23, pb23, v1.y);
        ADD_F32X2(pa01, pa01, v2.x); ADD_F32X2(pa23, pa23, v2.y);
        ADD_F32X2(pb01, pb01, v3.x); ADD_F32X2(pb23, pb23, v3.y);
        ADD_F32X2(pa01, pa01, v4.x); ADD_F32X2(pa23, pa23, v4.y);
        ADD_F32X2(pb01, pb01, v5.x); ADD_F32X2(pb23, pb23, v5.y);
        ADD_F32X2(pa01, pa01, v6.x); ADD_F32X2(pa23, pa23, v6.y);
        ADD_F32X2(pb01, pb01, v7.x); ADD_F32X2(pb23, pb23, v7.y);
    }
#pragma unroll 1
    for (; e < end; e++) {
        int s0 = __ldg(&g_esrc[e]);
        ulonglong2 v = in2[(size_t)s0 * 32 + lane];
        ADD_F32X2(pa01, pa01, v.x); ADD_F32X2(pa23, pa23, v.y);
    }
    ADD_F32X2(pa01, pa01, pb01);
    ADD_F32X2(pa23, pa23, pb23);
    float f0, f1, f2, f3;
    UNPACK_F32X2(f0, f1, pa01);
    UNPACK_F32X2(f2, f3, pa23);
    float inv = (dcnt > 0) ? 1.0f / (float)dcnt : 0.0f;
    f0 *= inv; f1 *= inv; f2 *= inv; f3 *= inv;
    __nv_bfloat162 h01 = __floats2bfloat162_rn(f0, f1);
    __nv_bfloat162 h23 = __floats2bfloat162_rn(f2, f3);
    __nv_bfloat162 l01 = __floats2bfloat162_rn(f0 - __bfloat162float(h01.x),
                                               f1 - __bfloat162float(h01.y));
    __nv_bfloat162 l23 = __floats2bfloat162_rn(f2 - __bfloat162float(h23.x),
                                               f3 - __bfloat162float(h23.y));
    ((uint2*)outH)[w * 32 + lane] = make_uint2(bf2u(h01), bf2u(h23));
    ((uint2*)outL)[w * 32 + lane] = make_uint2(bf2u(l01), bf2u(l23));
}

// ---------------- mma.sync SAGE GEMM: A-fill is a pure bf16 plane copy ----------------
#define SA_STRIDE 72   // bf16 elems per row (144B), conflict-free ldmatrix
__global__ void __launch_bounds__(256, 2)
k_gemm_mma(const __nv_bfloat16* __restrict__ AgH, const __nv_bfloat16* __restrict__ AgL,
           const __nv_bfloat16* __restrict__ BxH, const __nv_bfloat16* __restrict__ BxL,
           const uint2* __restrict__ WfH, const uint2* __restrict__ WfL,
           const float* __restrict__ bias, float* __restrict__ out,
           __nv_bfloat16* __restrict__ outH, __nv_bfloat16* __restrict__ outL) {
    __shared__ __nv_bfloat16 sAh[128 * SA_STRIDE];
    __shared__ __nv_bfloat16 sAl[128 * SA_STRIDE];
    int tid = threadIdx.x;
    int wid = tid >> 5, lane = tid & 31;
    int m0 = blockIdx.x * 128;
    int wm = wid & 3, wn = wid >> 2;

    float acc[2][8][4];
#pragma unroll
    for (int a = 0; a < 2; a++)
#pragma unroll
        for (int b = 0; b < 8; b++)
#pragma unroll
            for (int q = 0; q < 4; q++) acc[a][b][q] = 0.f;

    int frow = tid >> 1, fhalf = tid & 1;   // pad rows are zero -> no guard needed

    int g = lane >> 3, ri = lane & 7;
    uint32_t sAh_u = smem_to_u32(sAh);
    uint32_t sAl_u = smem_to_u32(sAl);

#pragma unroll 1
    for (int c = 0; c < 4; c++) {
        const __nv_bfloat16* srcH = (c < 2) ? AgH : BxH;
        const __nv_bfloat16* srcL = (c < 2) ? AgL : BxL;
        int kcol = (c & 1) * 64;
        const uint4* pH = (const uint4*)(srcH + (size_t)(m0 + frow) * DD + kcol + fhalf * 32);
        const uint4* pL = (const uint4*)(srcL + (size_t)(m0 + frow) * DD + kcol + fhalf * 32);
        __nv_bfloat16* dH = sAh + (uint32_t)frow * SA_STRIDE + (uint32_t)fhalf * 32;
        __nv_bfloat16* dL = sAl + (uint32_t)frow * SA_STRIDE + (uint32_t)fhalf * 32;
#pragma unroll
        for (int q = 0; q < 4; q++) {
            *(uint4*)(dH + q * 8) = pH[q];
            *(uint4*)(dL + q * 8) = pL[q];
        }
        __syncthreads();

#pragma unroll
        for (int ss = 0; ss < 4; ss++) {
            int s = c * 4 + ss;
            int k0 = ss * 16;
            uint32_t Ah[2][4], Al[2][4];
#pragma unroll
            for (int mt = 0; mt < 2; mt++) {
                uint32_t row = (uint32_t)(wm * 32 + mt * 16 + (g & 1) * 8 + ri);
                uint32_t byo = (row * SA_STRIDE + (uint32_t)(k0 + (g >> 1) * 8)) * 2;
                LDM_X4(Ah[mt], sAh_u + byo);
                LDM_X4(Al[mt], sAl_u + byo);
            }
#pragma unroll
            for (int nt = 0; nt < 8; nt++) {
                int idx = (((wn * 8 + nt) * 16 + s) << 5) + lane;
                uint2 bh = __ldg(&WfH[idx]);
                uint2 bl = __ldg(&WfL[idx]);
                MMA_BF16(acc[0][nt], Ah[0], bh);
                MMA_BF16(acc[1][nt], Ah[1], bh);
                MMA_BF16(acc[0][nt], Al[0], bh);
                MMA_BF16(acc[1][nt], Al[1], bh);
                MMA_BF16(acc[0][nt], Ah[0], bl);
                MMA_BF16(acc[1][nt], Ah[1], bl);
            }
        }
        __syncthreads();
    }

    int r_in = lane >> 2;
    int n_in = (lane & 3) * 2;
#pragma unroll
    for (int nt = 0; nt < 8; nt++) {
        int n = wn * 64 + nt * 8 + n_in;
        float2 bb = *(const float2*)(bias + n);
#pragma unroll
        for (int mt = 0; mt < 2; mt++) {
            int r0 = m0 + wm * 32 + mt * 16 + r_in;
            if (r0 < NN) {
                float2 o;
                o.x = fmaxf(acc[mt][nt][0] + bb.x, 0.f);
                o.y = fmaxf(acc[mt][nt][1] + bb.y, 0.f);
                *(float2*)(out + (size_t)r0 * DD + n) = o;
                if (outH) {
                    __nv_bfloat162 h = __floats2bfloat162_rn(o.x, o.y);
                    __nv_bfloat162 l = __floats2bfloat162_rn(o.x - __bfloat162float(h.x),
                                                             o.y - __bfloat162float(h.y));
                    *(uint32_t*)(outH + (size_t)r0 * DD + n) = bf2u(h);
                    *(uint32_t*)(outL + (size_t)r0 * DD + n) = bf2u(l);
                }
            }
            int r1 = r0 + 8;
            if (r1 < NN) {
                float2 o;
                o.x = fmaxf(acc[mt][nt][2] + bb.x, 0.f);
                o.y = fmaxf(acc[mt][nt][3] + bb.y, 0.f);
                *(float2*)(out + (size_t)r1 * DD + n) = o;
                if (outH) {
                    __nv_bfloat162 h = __floats2bfloat162_rn(o.x, o.y);
                    __nv_bfloat162 l = __floats2bfloat162_rn(o.x - __bfloat162float(h.x),
                                                             o.y - __bfloat162float(h.y));
                    *(uint32_t*)(outH + (size_t)r1 * DD + n) = bf2u(h);
                    *(uint32_t*)(outL + (size_t)r1 * DD + n) = bf2u(l);
                }
            }
        }
    }
}

// ---------------- global add pool (batch is sorted, int32) ----------------
#define NPB 256
__global__ void k_pool(const float* __restrict__ h, const int* __restrict__ batch) {
    int t = threadIdx.x;
    int start = blockIdx.x * NPB;
    int end = start + NPB; if (end > NN) end = NN;
    if (start >= NN) return;
    int cur = batch[start];
    float sum = 0.f;
    for (int i = start; i < end; i++) {
        int b = __ldg(&batch[i]);
        if (b != cur) {
            atomicAdd(&g_pool[cur * DD + t], sum);
            sum = 0.f; cur = b;
        }
        sum += h[(size_t)i * DD + t];
    }
    atomicAdd(&g_pool[cur * DD + t], sum);
}

// ---------------- LayerNorm + final linear + scratch re-zero for next replay ----
__global__ void k_final(const float* __restrict__ ln_g, const float* __restrict__ ln_b,
                        const float* __restrict__ Wlin, const float* __restrict__ blin,
                        float* __restrict__ out) {
    int gtid = blockIdx.x * blockDim.x + threadIdx.x;
    int w = gtid >> 5;
    int lane = threadIdx.x & 31;
    if (w < NG) {
        float4 v = ((const float4*)g_pool)[w * 32 + lane];
        float s = v.x + v.y + v.z + v.w;
#pragma unroll
        for (int o = 16; o; o >>= 1) s += __shfl_xor_sync(0xffffffffu, s, o);
        float mean = s * (1.0f / 128.0f);
        float dx = v.x - mean, dy = v.y - mean, dz = v.z - mean, dw = v.w - mean;
        float q = dx * dx + dy * dy + dz * dz + dw * dw;
#pragma unroll
        for (int o = 16; o; o >>= 1) q += __shfl_xor_sync(0xffffffffu, q, o);
        float var = q * (1.0f / 128.0f);
        float r = rsqrtf(var + 1e-5f);
        float4 gg = ((const float4*)ln_g)[lane];
        float4 bb = ((const float4*)ln_b)[lane];
        float n0 = dx * r * gg.x + bb.x;
        float n1 = dy * r * gg.y + bb.y;
        float n2 = dz * r * gg.z + bb.z;
        float n3 = dw * r * gg.w + bb.w;
        float4 w0 = ((const float4*)Wlin)[lane];
        float4 w1 = ((const float4*)Wlin)[32 + lane];
        float d0 = n0 * w0.x + n1 * w0.y + n2 * w0.z + n3 * w0.w;
        float d1 = n0 * w1.x + n1 * w1.y + n2 * w1.z + n3 * w1.w;
#pragma unroll
        for (int o = 16; o; o >>= 1) {
            d0 += __shfl_xor_sync(0xffffffffu, d0, o);
            d1 += __shfl_xor_sync(0xffffffffu, d1, o);
        }
        if (lane == 0) {
            out[w * 2 + 0] = d0 + blin[0];
            out[w * 2 + 1] = d1 + blin[1];
        }
        // this warp is the only reader of g_pool[w] -> race-free re-zero
        ((float4*)g_pool)[w * 32 + lane] = make_float4(0.f, 0.f, 0.f, 0.f);
    }
    if (gtid == 0) g_alloc = 0;
    // re-zero deg/cursor for next replay (NG*32 = 32768 threads total)
    for (int i = gtid; i < NN; i += NG * 32) { g_deg[i] = 0; g_cursor[i] = 0; }
}

// ---------------- launch ----------------
extern "C" void kernel_launch(void* const* d_in, const int* in_sizes, int n_in,
                              void* d_out, int out_size) {
    const float* x     = (const float*)d_in[0];
    const int*   ei    = (const int*)d_in[1];
    const int*   bat   = (const int*)d_in[2];
    const float* W1l   = (const float*)d_in[3];
    const float* b1l   = (const float*)d_in[4];
    const float* W1r   = (const float*)d_in[5];
    const float* W2l   = (const float*)d_in[6];
    const float* b2l   = (const float*)d_in[7];
    const float* W2r   = (const float*)d_in[8];
    const float* ln_g  = (const float*)d_in[9];
    const float* ln_b  = (const float*)d_in[10];
    const float* Wlin  = (const float*)d_in[11];
    const float* blin  = (const float*)d_in[12];

    const int* src = ei;
    const int* dst = ei + NE;

    float *h1, *h2;
    __nv_bfloat16 *xH, *xL, *aH, *aL, *hH, *hL;
    uint2 *wfh, *wfl;
    cudaGetSymbolAddress((void**)&h1,  g_h1);
    cudaGetSymbolAddress((void**)&h2,  g_h2);
    cudaGetSymbolAddress((void**)&xH,  g_xH);
    cudaGetSymbolAddress((void**)&xL,  g_xL);
    cudaGetSymbolAddress((void**)&aH,  g_aH);
    cudaGetSymbolAddress((void**)&aL,  g_aL);
    cudaGetSymbolAddress((void**)&hH,  g_hH);
    cudaGetSymbolAddress((void**)&hL,  g_hL);
    cudaGetSymbolAddress((void**)&wfh, g_WfH);
    cudaGetSymbolAddress((void**)&wfl, g_WfL);

    int degblks = (NE + 255) / 256;
    k_prep_deg<<<PREP_XB_BLKS + PREP_WF_BLKS + degblks, 256>>>(x, W1l, W1r, W2l, W2r, dst);  // 0
    k_alloc<<<NB_SCAN, 256>>>();                                                              // 1
    k_scatter<<<degblks, 256>>>(src, dst);                                                    // 2

    int nblk = (NN + 127) / 128;
    const int LSTRIDE = 16 * 16 * 32;
    k_agg<<<(NN * 32 + 255) / 256, 256>>>(x, aH, aL);                                         // 3 (profiled)
    k_gemm_mma<<<nblk, 256>>>(aH, aL, xH, xL, wfh, wfl, b1l, h1, hH, hL);                     // 4
    k_agg<<<(NN * 32 + 255) / 256, 256>>>(h1, aH, aL);                                        // 5
    k_gemm_mma<<<nblk, 256>>>(aH, aL, hH, hL, wfh + LSTRIDE, wfl + LSTRIDE, b2l, h2,
                              (__nv_bfloat16*)nullptr, (__nv_bfloat16*)nullptr);              // 6

    k_pool<<<(NN + NPB - 1) / NPB, 128>>>(h2, bat);                                           // 7
    k_final<<<(NG * 32 + 255) / 256, 256>>>(ln_g, ln_b, Wlin, blin, (float*)d_out);           // 8
}

// round 11
// speedup vs baseline: 1.1733x; 1.1733x over previous
#include <cuda_runtime.h>
#include <cuda_bf16.h>
#include <cstdint>

#define NN 100000
#define NPAD 100096   // 782*128, pad rows stay zero forever
#define NE 1600000
#define NG 1024
#define DD 128
#define NB_SCAN 391   // ceil(NN/256)

// ---------------- scratch (device globals; zero-initialized at load; k_final's
// tail re-zeros deg/cursor/alloc/pool; plane pad rows are never written) -------
__device__ __nv_bfloat16 g_xH[NPAD * DD];
__device__ __nv_bfloat16 g_xL[NPAD * DD];
__device__ __nv_bfloat16 g_hH[NPAD * DD];   // h1 hi plane (gemm2 A)
__device__ __nv_bfloat16 g_hL[NPAD * DD];
__device__ __nv_bfloat16 g_yB[NPAD * DD];   // Y = src@Wl^T, bf16 (gather source)
__device__ float g_z[NN * DD];              // Z = src@Wr^T, fp32
__device__ float g_h2[NN * DD];
__device__ float g_pool[NG * DD];
// W frags interleaved: [layer][j 0..31][s 0..7][lane] -> uint4 {bh01,bh23,bl01,bl23}
__device__ uint4 g_Wf[2 * 32 * 8 * 32];
__device__ int   g_deg[NN];
__device__ int   g_rowptr[NN];
__device__ int   g_cursor[NN];
__device__ int   g_esrc[NE];
__device__ int   g_alloc;

// ---------------- helpers ----------------
__device__ __forceinline__ uint32_t smem_to_u32(const void* p) {
    uint32_t a;
    asm("{ .reg .u64 t; cvta.to.shared.u64 t, %1; cvt.u32.u64 %0, t; }" : "=r"(a) : "l"(p));
    return a;
}
__device__ __forceinline__ uint32_t bf2u(__nv_bfloat162 v) { return *reinterpret_cast<uint32_t*>(&v); }

#define LDM_X4(r, addr) \
    asm volatile("ldmatrix.sync.aligned.m8n8.x4.shared.b16 {%0,%1,%2,%3}, [%4];" \
        : "=r"((r)[0]), "=r"((r)[1]), "=r"((r)[2]), "=r"((r)[3]) : "r"(addr))

#define MMA_BF16(c, b0, b1, a) \
    asm volatile("mma.sync.aligned.m16n8k16.row.col.f32.bf16.bf16.f32 " \
        "{%0,%1,%2,%3}, {%4,%5,%6,%7}, {%8,%9}, {%0,%1,%2,%3};" \
        : "+f"((c)[0]), "+f"((c)[1]), "+f"((c)[2]), "+f"((c)[3]) \
        : "r"((a)[0]), "r"((a)[1]), "r"((a)[2]), "r"((a)[3]), "r"(b0), "r"(b1))

// ---------------- slot 0: prep (x->hi/lo planes, W frag interleave) + degree ----
#define PREP_XB_BLKS 12500   // NN*DD/4 / 256
#define PREP_WF_BLKS 64      // 2*32*8*32 / 256
__global__ void k_prep_deg(const float* __restrict__ x,
                           const float* __restrict__ W1l, const float* __restrict__ W1r,
                           const float* __restrict__ W2l, const float* __restrict__ W2r,
                           const int* __restrict__ dst) {
    if (blockIdx.x < PREP_XB_BLKS) {
        int i = blockIdx.x * 256 + threadIdx.x;
        float4 f = ((const float4*)x)[i];
        __nv_bfloat162 h01 = __floats2bfloat162_rn(f.x, f.y);
        __nv_bfloat162 h23 = __floats2bfloat162_rn(f.z, f.w);
        __nv_bfloat162 l01 = __floats2bfloat162_rn(f.x - __bfloat162float(h01.x),
                                                   f.y - __bfloat162float(h01.y));
        __nv_bfloat162 l23 = __floats2bfloat162_rn(f.z - __bfloat162float(h23.x),
                                                   f.w - __bfloat162float(h23.y));
        ((uint2*)g_xH)[i] = make_uint2(bf2u(h01), bf2u(h23));
        ((uint2*)g_xL)[i] = make_uint2(bf2u(l01), bf2u(l23));
        return;
    }
    if (blockIdx.x < PREP_XB_BLKS + PREP_WF_BLKS) {
        int i = (blockIdx.x - PREP_XB_BLKS) * 256 + threadIdx.x;   // 0 .. 16383
        int lane = i & 31;
        int s = (i >> 5) & 7;         // k-step 0..7 (K=128)
        int j = (i >> 8) & 31;        // n-tile 0..31 (N=256: j<16 -> Wl, else Wr)
        int layer = i >> 13;
        int n = (j & 15) * 8 + (lane >> 2);
        int k = s * 16 + (lane & 3) * 2;
        const float* Wl = layer ? W2l : W1l;
        const float* Wr = layer ? W2r : W1r;
        const float* W = (j < 16) ? Wl : Wr;
        float w[4];
#pragma unroll
        for (int q = 0; q < 4; q++) {
            int kk = k + (q >> 1) * 8 + (q & 1);
            w[q] = W[n * DD + kk];
        }
        __nv_bfloat16 h[4], l[4];
#pragma unroll
        for (int q = 0; q < 4; q++) {
            h[q] = __float2bfloat16(w[q]);
            l[q] = __float2bfloat16(w[q] - __bfloat162float(h[q]));
        }
        __nv_bfloat162 h01; h01.x = h[0]; h01.y = h[1];
        __nv_bfloat162 h23; h23.x = h[2]; h23.y = h[3];
        __nv_bfloat162 l01; l01.x = l[0]; l01.y = l[1];
        __nv_bfloat162 l23; l23.x = l[2]; l23.y = l[3];
        g_Wf[i] = make_uint4(bf2u(h01), bf2u(h23), bf2u(l01), bf2u(l23));
        return;
    }
    int i = (blockIdx.x - PREP_XB_BLKS - PREP_WF_BLKS) * 256 + threadIdx.x;
    if (i < NE) atomicAdd(&g_deg[dst[i]], 1);
}

// ---------------- slot 1: bucket allocation ----------------
__global__ void k_alloc() {
    __shared__ int s[256];
    __shared__ int base;
    int b = blockIdx.x, t = threadIdx.x;
    int i = b * 256 + t;
    int v = (i < NN) ? g_deg[i] : 0;
    s[t] = v;
    __syncthreads();
#pragma unroll
    for (int off = 1; off < 256; off <<= 1) {
        int add = (t >= off) ? s[t - off] : 0;
        __syncthreads();
        s[t] += add;
        __syncthreads();
    }
    if (t == 255) base = atomicAdd(&g_alloc, s[255]);
    __syncthreads();
    if (i < NN) g_rowptr[i] = base + s[t] - v;
}

// ---------------- slot 2: scatter edges into buckets ----------------
__global__ void k_scatter(const int* __restrict__ src, const int* __restrict__ dst) {
    int i = blockIdx.x * blockDim.x + threadIdx.x;
    if (i >= NE) return;
    int d = dst[i];
    int pos = atomicAdd(&g_cursor[d], 1);
    g_esrc[g_rowptr[d] + pos] = src[i];
}

// ---------------- slot 3 (PROFILED): GEMM  [Y|Z] = A @ [Wl;Wr]^T ----------------
// A from bf16 hi/lo planes, K=128 (2 chunks), N=256 via blockIdx.y (128 each).
// 3-term split: D = Ah*Wh + Al*Wh + Ah*Wl. y-half stored bf16, z-half fp32. No bias.
#define SA_STRIDE 72
__global__ void __launch_bounds__(256, 2)
k_gemm(const __nv_bfloat16* __restrict__ AH, const __nv_bfloat16* __restrict__ AL,
       const uint4* __restrict__ Wf,
       __nv_bfloat16* __restrict__ yB, float* __restrict__ z) {
    __shared__ __nv_bfloat16 sAh[128 * SA_STRIDE];
    __shared__ __nv_bfloat16 sAl[128 * SA_STRIDE];
    int tid = threadIdx.x;
    int wid = tid >> 5, lane = tid & 31;
    int m0 = blockIdx.x * 128;
    int wm = wid & 3, wn = wid >> 2;
    int jbase = blockIdx.y * 16;

    float acc[2][8][4];
#pragma unroll
    for (int a = 0; a < 2; a++)
#pragma unroll
        for (int b = 0; b < 8; b++)
#pragma unroll
            for (int q = 0; q < 4; q++) acc[a][b][q] = 0.f;

    int frow = tid >> 1, fhalf = tid & 1;   // plane pad rows are zero -> no guard
    int g = lane >> 3, ri = lane & 7;
    uint32_t sAh_u = smem_to_u32(sAh);
    uint32_t sAl_u = smem_to_u32(sAl);

#pragma unroll 1
    for (int c = 0; c < 2; c++) {
        int kcol = c * 64;
        const uint4* pH = (const uint4*)(AH + (size_t)(m0 + frow) * DD + kcol + fhalf * 32);
        const uint4* pL = (const uint4*)(AL + (size_t)(m0 + frow) * DD + kcol + fhalf * 32);
        __nv_bfloat16* dH = sAh + (uint32_t)frow * SA_STRIDE + (uint32_t)fhalf * 32;
        __nv_bfloat16* dL = sAl + (uint32_t)frow * SA_STRIDE + (uint32_t)fhalf * 32;
#pragma unroll
        for (int q = 0; q < 4; q++) {
            *(uint4*)(dH + q * 8) = pH[q];
            *(uint4*)(dL + q * 8) = pL[q];
        }
        __syncthreads();

#pragma unroll
        for (int ss = 0; ss < 4; ss++) {
            int s = c * 4 + ss;
            int k0 = ss * 16;
            uint32_t Ah[2][4], Al[2][4];
#pragma unroll
            for (int mt = 0; mt < 2; mt++) {
                uint32_t row = (uint32_t)(wm * 32 + mt * 16 + (g & 1) * 8 + ri);
                uint32_t byo = (row * SA_STRIDE + (uint32_t)(k0 + (g >> 1) * 8)) * 2;
                LDM_X4(Ah[mt], sAh_u + byo);
                LDM_X4(Al[mt], sAl_u + byo);
            }
#pragma unroll
            for (int nt = 0; nt < 8; nt++) {
                int j = jbase + wn * 8 + nt;
                uint4 wv = __ldg(&Wf[((j * 8 + s) << 5) + lane]);
                MMA_BF16(acc[0][nt], wv.x, wv.y, Ah[0]);
                MMA_BF16(acc[1][nt], wv.x, wv.y, Ah[1]);
                MMA_BF16(acc[0][nt], wv.x, wv.y, Al[0]);
                MMA_BF16(acc[1][nt], wv.x, wv.y, Al[1]);
                MMA_BF16(acc[0][nt], wv.z, wv.w, Ah[0]);
                MMA_BF16(acc[1][nt], wv.z, wv.w, Ah[1]);
            }
        }
        __syncthreads();
    }

    // epilogue: y-half (blockIdx.y==0) -> bf16, z-half -> fp32; no bias
    int r_in = lane >> 2;
    int n_in = (lane & 3) * 2;
    bool isY = (blockIdx.y == 0);
#pragma unroll
    for (int nt = 0; nt < 8; nt++) {
        int n = wn * 64 + nt * 8 + n_in;   // 0..127 within half
#pragma unroll
        for (int mt = 0; mt < 2; mt++) {
            int r0 = m0 + wm * 32 + mt * 16 + r_in;
            if (r0 < NN) {
                if (isY) {
                    __nv_bfloat162 o = __floats2bfloat162_rn(acc[mt][nt][0], acc[mt][nt][1]);
                    *(uint32_t*)(yB + (size_t)r0 * DD + n) = bf2u(o);
                } else {
                    *(float2*)(z + (size_t)r0 * DD + n) = make_float2(acc[mt][nt][0], acc[mt][nt][1]);
                }
            }
            int r1 = r0 + 8;
            if (r1 < NN) {
                if (isY) {
                    __nv_bfloat162 o = __floats2bfloat162_rn(acc[mt][nt][2], acc[mt][nt][3]);
                    *(uint32_t*)(yB + (size_t)r1 * DD + n) = bf2u(o);
                } else {
                    *(float2*)(z + (size_t)r1 * DD + n) = make_float2(acc[mt][nt][2], acc[mt][nt][3]);
                }
            }
        }
    }
}

// ---------------- fused agg + epilogue: h = relu(mean_nb(Y) + Z + bias) ----------
// warp per node; bf16 Y gather (R9-proven loop); writes hi/lo planes (layer1)
// or fp32 (layer2).
__global__ void k_aggf(const float* __restrict__ z, const float* __restrict__ bias,
                       __nv_bfloat16* __restrict__ outH, __nv_bfloat16* __restrict__ outL,
                       float* __restrict__ outF) {
    int w = (blockIdx.x * blockDim.x + threadIdx.x) >> 5;
    int lane = threadIdx.x & 31;
    if (w >= NN) return;
    int beg = g_rowptr[w];
    int dcnt = g_deg[w];
    int end = beg + dcnt;
    const uint2* in2 = (const uint2*)g_yB;
    float a0 = 0.f, a1 = 0.f, a2 = 0.f, a3 = 0.f;
    int e = beg;
#pragma unroll 1
    for (; e + 7 < end; e += 8) {
        int s0 = __ldg(&g_esrc[e]);
        int s1 = __ldg(&g_esrc[e + 1]);
        int s2 = __ldg(&g_esrc[e + 2]);
        int s3 = __ldg(&g_esrc[e + 3]);
        int s4 = __ldg(&g_esrc[e + 4]);
        int s5 = __ldg(&g_esrc[e + 5]);
        int s6 = __ldg(&g_esrc[e + 6]);
        int s7 = __ldg(&g_esrc[e + 7]);
        uint2 v0 = __ldg(&in2[(size_t)s0 * 32 + lane]);
        uint2 v1 = __ldg(&in2[(size_t)s1 * 32 + lane]);
        uint2 v2 = __ldg(&in2[(size_t)s2 * 32 + lane]);
        uint2 v3 = __ldg(&in2[(size_t)s3 * 32 + lane]);
        uint2 v4 = __ldg(&in2[(size_t)s4 * 32 + lane]);
        uint2 v5 = __ldg(&in2[(size_t)s5 * 32 + lane]);
        uint2 v6 = __ldg(&in2[(size_t)s6 * 32 + lane]);
        uint2 v7 = __ldg(&in2[(size_t)s7 * 32 + lane]);
#pragma unroll
        for (int q = 0; q < 8; q++) {
            uint2 v = q == 0 ? v0 : q == 1 ? v1 : q == 2 ? v2 : q == 3 ? v3
                    : q == 4 ? v4 : q == 5 ? v5 : q == 6 ? v6 : v7;
            float2 p0 = __bfloat1622float2(*(__nv_bfloat162*)&v.x);
            float2 p1 = __bfloat1622float2(*(__nv_bfloat162*)&v.y);
            a0 += p0.x; a1 += p0.y; a2 += p1.x; a3 += p1.y;
        }
    }
    for (; e < end; e++) {
        int s0 = __ldg(&g_esrc[e]);
        uint2 v = __ldg(&in2[(size_t)s0 * 32 + lane]);
        float2 p0 = __bfloat1622float2(*(__nv_bfloat162*)&v.x);
        float2 p1 = __bfloat1622float2(*(__nv_bfloat162*)&v.y);
        a0 += p0.x; a1 += p0.y; a2 += p1.x; a3 += p1.y;
    }
    float inv = (dcnt > 0) ? 1.0f / (float)dcnt : 0.0f;
    float4 zz = ((const float4*)z)[w * 32 + lane];
    float4 bb = ((const float4*)bias)[lane];
    float f0 = fmaxf(a0 * inv + zz.x + bb.x, 0.f);
    float f1 = fmaxf(a1 * inv + zz.y + bb.y, 0.f);
    float f2 = fmaxf(a2 * inv + zz.z + bb.z, 0.f);
    float f3 = fmaxf(a3 * inv + zz.w + bb.w, 0.f);
    if (outF) {
        ((float4*)outF)[w * 32 + lane] = make_float4(f0, f1, f2, f3);
    } else {
        __nv_bfloat162 h01 = __floats2bfloat162_rn(f0, f1);
        __nv_bfloat162 h23 = __floats2bfloat162_rn(f2, f3);
        __nv_bfloat162 l01 = __floats2bfloat162_rn(f0 - __bfloat162float(h01.x),
                                                   f1 - __bfloat162float(h01.y));
        __nv_bfloat162 l23 = __floats2bfloat162_rn(f2 - __bfloat162float(h23.x),
                                                   f3 - __bfloat162float(h23.y));
        ((uint2*)outH)[w * 32 + lane] = make_uint2(bf2u(h01), bf2u(h23));
        ((uint2*)outL)[w * 32 + lane] = make_uint2(bf2u(l01), bf2u(l23));
    }
}

// ---------------- global add pool (batch is sorted, int32) ----------------
#define NPB 256
__global__ void k_pool(const float* __restrict__ h, const int* __restrict__ batch) {
    int t = threadIdx.x;
    int start = blockIdx.x * NPB;
    int end = start + NPB; if (end > NN) end = NN;
    if (start >= NN) return;
    int cur = batch[start];
    float sum = 0.f;
    for (int i = start; i < end; i++) {
        int b = __ldg(&batch[i]);
        if (b != cur) {
            atomicAdd(&g_pool[cur * DD + t], sum);
            sum = 0.f; cur = b;
        }
        sum += h[(size_t)i * DD + t];
    }
    atomicAdd(&g_pool[cur * DD + t], sum);
}

// ---------------- LayerNorm + final linear + scratch re-zero ----------------
__global__ void k_final(const float* __restrict__ ln_g, const float* __restrict__ ln_b,
                        const float* __restrict__ Wlin, const float* __restrict__ blin,
                        float* __restrict__ out) {
    int gtid = blockIdx.x * blockDim.x + threadIdx.x;
    int w = gtid >> 5;
    int lane = threadIdx.x & 31;
    if (w < NG) {
        float4 v = ((const float4*)g_pool)[w * 32 + lane];
        float s = v.x + v.y + v.z + v.w;
#pragma unroll
        for (int o = 16; o; o >>= 1) s += __shfl_xor_sync(0xffffffffu, s, o);
        float mean = s * (1.0f / 128.0f);
        float dx = v.x - mean, dy = v.y - mean, dz = v.z - mean, dw = v.w - mean;
        float q = dx * dx + dy * dy + dz * dz + dw * dw;
#pragma unroll
        for (int o = 16; o; o >>= 1) q += __shfl_xor_sync(0xffffffffu, q, o);
        float var = q * (1.0f / 128.0f);
        float r = rsqrtf(var + 1e-5f);
        float4 gg = ((const float4*)ln_g)[lane];
        float4 bb = ((const float4*)ln_b)[lane];
        float n0 = dx * r * gg.x + bb.x;
        float n1 = dy * r * gg.y + bb.y;
        float n2 = dz * r * gg.z + bb.z;
        float n3 = dw * r * gg.w + bb.w;
        float4 w0 = ((const float4*)Wlin)[lane];
        float4 w1 = ((const float4*)Wlin)[32 + lane];
        float d0 = n0 * w0.x + n1 * w0.y + n2 * w0.z + n3 * w0.w;
        float d1 = n0 * w1.x + n1 * w1.y + n2 * w1.z + n3 * w1.w;
#pragma unroll
        for (int o = 16; o; o >>= 1) {
            d0 += __shfl_xor_sync(0xffffffffu, d0, o);
            d1 += __shfl_xor_sync(0xffffffffu, d1, o);
        }
        if (lane == 0) {
            out[w * 2 + 0] = d0 + blin[0];
            out[w * 2 + 1] = d1 + blin[1];
        }
        ((float4*)g_pool)[w * 32 + lane] = make_float4(0.f, 0.f, 0.f, 0.f);
    }
    if (gtid == 0) g_alloc = 0;
    for (int i = gtid; i < NN; i += NG * 32) { g_deg[i] = 0; g_cursor[i] = 0; }
}

// ---------------- launch ----------------
extern "C" void kernel_launch(void* const* d_in, const int* in_sizes, int n_in,
                              void* d_out, int out_size) {
    const float* x     = (const float*)d_in[0];
    const int*   ei    = (const int*)d_in[1];
    const int*   bat   = (const int*)d_in[2];
    const float* W1l   = (const float*)d_in[3];
    const float* b1l   = (const float*)d_in[4];
    const float* W1r   = (const float*)d_in[5];
    const float* W2l   = (const float*)d_in[6];
    const float* b2l   = (const float*)d_in[7];
    const float* W2r   = (const float*)d_in[8];
    const float* ln_g  = (const float*)d_in[9];
    const float* ln_b  = (const float*)d_in[10];
    const float* Wlin  = (const float*)d_in[11];
    const float* blin  = (const float*)d_in[12];

    const int* src = ei;
    const int* dst = ei + NE;

    __nv_bfloat16 *xH, *xL, *hH, *hL, *yB;
    float *z, *h2;
    uint4* wf;
    cudaGetSymbolAddress((void**)&xH, g_xH);
    cudaGetSymbolAddress((void**)&xL, g_xL);
    cudaGetSymbolAddress((void**)&hH, g_hH);
    cudaGetSymbolAddress((void**)&hL, g_hL);
    cudaGetSymbolAddress((void**)&yB, g_yB);
    cudaGetSymbolAddress((void**)&z,  g_z);
    cudaGetSymbolAddress((void**)&h2, g_h2);
    cudaGetSymbolAddress((void**)&wf, g_Wf);

    int degblks = (NE + 255) / 256;
    k_prep_deg<<<PREP_XB_BLKS + PREP_WF_BLKS + degblks, 256>>>(x, W1l, W1r, W2l, W2r, dst);  // 0
    k_alloc<<<NB_SCAN, 256>>>();                                                              // 1
    k_scatter<<<degblks, 256>>>(src, dst);                                                    // 2

    const int LSTRIDE = 32 * 8 * 32;   // uint4 per layer
    dim3 ggrid((NN + 127) / 128, 2);
    k_gemm<<<ggrid, 256>>>(xH, xL, wf, yB, z);                                                // 3 (profiled)
    k_aggf<<<(NN * 32 + 255) / 256, 256>>>(z, b1l, hH, hL, (float*)nullptr);                  // 4
    k_gemm<<<ggrid, 256>>>(hH, hL, wf + LSTRIDE, yB, z);                                      // 5
    k_aggf<<<(NN * 32 + 255) / 256, 256>>>(z, b2l, (__nv_bfloat16*)nullptr,
                                           (__nv_bfloat16*)nullptr, h2);                      // 6

    k_pool<<<(NN + NPB - 1) / NPB, 128>>>(h2, bat);                                           // 7
    k_final<<<(NG * 32 + 255) / 256, 256>>>(ln_g, ln_b, Wlin, blin, (float*)d_out);           // 8
}

// round 12
// speedup vs baseline: 1.1742x; 1.0007x over previous
#include <cuda_runtime.h>
#include <cuda_bf16.h>
#include <cstdint>

#define NN 100000
#define NPAD 100096   // 782*128, pad rows stay zero forever
#define NE 1600000
#define NG 1024
#define DD 128
#define NB_SCAN 391   // ceil(NN/256)

// ---------------- scratch (device globals; zero-initialized at load; k_final's
// tail re-zeros deg/cursor/alloc/pool; plane pad rows are never written) -------
__device__ __nv_bfloat16 g_xH[NPAD * DD];
__device__ __nv_bfloat16 g_xL[NPAD * DD];
__device__ __nv_bfloat16 g_hH[NPAD * DD];   // h1 hi plane (gemm2 A)
__device__ __nv_bfloat16 g_hL[NPAD * DD];
__device__ __nv_bfloat16 g_yB[NPAD * DD];   // Y = src@Wl^T, bf16 (gather source)
__device__ float g_z[NN * DD];              // Z = src@Wr^T, fp32
__device__ float g_h2[NN * DD];
__device__ float g_pool[NG * DD];
// W frags interleaved: [layer][j 0..31][s 0..7][lane] -> uint4 {bh01,bh23,bl01,bl23}
__device__ uint4 g_Wf[2 * 32 * 8 * 32];
__device__ int   g_deg[NN];
__device__ int   g_rowptr[NN];
__device__ int   g_cursor[NN];
__device__ int   g_esrc[NE];
__device__ int   g_alloc;

// ---------------- helpers ----------------
__device__ __forceinline__ uint32_t smem_to_u32(const void* p) {
    uint32_t a;
    asm("{ .reg .u64 t; cvta.to.shared.u64 t, %1; cvt.u32.u64 %0, t; }" : "=r"(a) : "l"(p));
    return a;
}
__device__ __forceinline__ uint32_t bf2u(__nv_bfloat162 v) { return *reinterpret_cast<uint32_t*>(&v); }

#define LDM_X4(r, addr) \
    asm volatile("ldmatrix.sync.aligned.m8n8.x4.shared.b16 {%0,%1,%2,%3}, [%4];" \
        : "=r"((r)[0]), "=r"((r)[1]), "=r"((r)[2]), "=r"((r)[3]) : "r"(addr))

#define MMA_BF16(c, b0, b1, a) \
    asm volatile("mma.sync.aligned.m16n8k16.row.col.f32.bf16.bf16.f32 " \
        "{%0,%1,%2,%3}, {%4,%5,%6,%7}, {%8,%9}, {%0,%1,%2,%3};" \
        : "+f"((c)[0]), "+f"((c)[1]), "+f"((c)[2]), "+f"((c)[3]) \
        : "r"((a)[0]), "r"((a)[1]), "r"((a)[2]), "r"((a)[3]), "r"(b0), "r"(b1))

#define CP_ASYNC16(dst, src) \
    asm volatile("cp.async.cg.shared.global [%0], [%1], 16;" :: "r"(dst), "l"(src))
#define CP_COMMIT() asm volatile("cp.async.commit_group;" ::: "memory")
#define CP_WAIT(n)  asm volatile("cp.async.wait_group %0;" :: "n"(n) : "memory")

// ---------------- slot 0: prep (x->hi/lo planes, W frag interleave) + degree ----
#define PREP_XB_BLKS 12500   // NN*DD/4 / 256
#define PREP_WF_BLKS 64      // 2*32*8*32 / 256
__global__ void k_prep_deg(const float* __restrict__ x,
                           const float* __restrict__ W1l, const float* __restrict__ W1r,
                           const float* __restrict__ W2l, const float* __restrict__ W2r,
                           const int* __restrict__ dst) {
    if (blockIdx.x < PREP_XB_BLKS) {
        int i = blockIdx.x * 256 + threadIdx.x;
        float4 f = ((const float4*)x)[i];
        __nv_bfloat162 h01 = __floats2bfloat162_rn(f.x, f.y);
        __nv_bfloat162 h23 = __floats2bfloat162_rn(f.z, f.w);
        __nv_bfloat162 l01 = __floats2bfloat162_rn(f.x - __bfloat162float(h01.x),
                                                   f.y - __bfloat162float(h01.y));
        __nv_bfloat162 l23 = __floats2bfloat162_rn(f.z - __bfloat162float(h23.x),
                                                   f.w - __bfloat162float(h23.y));
        ((uint2*)g_xH)[i] = make_uint2(bf2u(h01), bf2u(h23));
        ((uint2*)g_xL)[i] = make_uint2(bf2u(l01), bf2u(l23));
        return;
    }
    if (blockIdx.x < PREP_XB_BLKS + PREP_WF_BLKS) {
        int i = (blockIdx.x - PREP_XB_BLKS) * 256 + threadIdx.x;   // 0 .. 16383
        int lane = i & 31;
        int s = (i >> 5) & 7;         // k-step 0..7 (K=128)
        int j = (i >> 8) & 31;        // n-tile 0..31 (N=256: j<16 -> Wl, else Wr)
        int layer = i >> 13;
        int n = (j & 15) * 8 + (lane >> 2);
        int k = s * 16 + (lane & 3) * 2;
        const float* Wl = layer ? W2l : W1l;
        const float* Wr = layer ? W2r : W1r;
        const float* W = (j < 16) ? Wl : Wr;
        float w[4];
#pragma unroll
        for (int q = 0; q < 4; q++) {
            int kk = k + (q >> 1) * 8 + (q & 1);
            w[q] = W[n * DD + kk];
        }
        __nv_bfloat16 h[4], l[4];
#pragma unroll
        for (int q = 0; q < 4; q++) {
            h[q] = __float2bfloat16(w[q]);
            l[q] = __float2bfloat16(w[q] - __bfloat162float(h[q]));
        }
        __nv_bfloat162 h01; h01.x = h[0]; h01.y = h[1];
        __nv_bfloat162 h23; h23.x = h[2]; h23.y = h[3];
        __nv_bfloat162 l01; l01.x = l[0]; l01.y = l[1];
        __nv_bfloat162 l23; l23.x = l[2]; l23.y = l[3];
        g_Wf[i] = make_uint4(bf2u(h01), bf2u(h23), bf2u(l01), bf2u(l23));
        return;
    }
    int i = (blockIdx.x - PREP_XB_BLKS - PREP_WF_BLKS) * 256 + threadIdx.x;
    if (i < NE) atomicAdd(&g_deg[dst[i]], 1);
}

// ---------------- slot 1: bucket allocation ----------------
__global__ void k_alloc() {
    __shared__ int s[256];
    __shared__ int base;
    int b = blockIdx.x, t = threadIdx.x;
    int i = b * 256 + t;
    int v = (i < NN) ? g_deg[i] : 0;
    s[t] = v;
    __syncthreads();
#pragma unroll
    for (int off = 1; off < 256; off <<= 1) {
        int add = (t >= off) ? s[t - off] : 0;
        __syncthreads();
        s[t] += add;
        __syncthreads();
    }
    if (t == 255) base = atomicAdd(&g_alloc, s[255]);
    __syncthreads();
    if (i < NN) g_rowptr[i] = base + s[t] - v;
}

// ---------------- slot 2: scatter edges into buckets ----------------
__global__ void k_scatter(const int* __restrict__ src, const int* __restrict__ dst) {
    int i = blockIdx.x * blockDim.x + threadIdx.x;
    if (i >= NE) return;
    int d = dst[i];
    int pos = atomicAdd(&g_cursor[d], 1);
    g_esrc[g_rowptr[d] + pos] = src[i];
}

// ---------------- slot 3 (PROFILED): GEMM  [Y|Z] = A @ [Wl;Wr]^T ----------------
// A from bf16 hi/lo planes via cp.async double buffer: both K-chunks' copies are
// issued up front; chunk-1 copy overlaps chunk-0 MMAs. 3-term split.
#define SA_STRIDE 72
#define SA_CHUNK (128 * SA_STRIDE)                 // bf16 elems per plane-chunk
#define SMEM_GEMM (4 * SA_CHUNK * 2)               // 2 chunks x 2 planes, bytes
__global__ void __launch_bounds__(256, 2)
k_gemm(const __nv_bfloat16* __restrict__ AH, const __nv_bfloat16* __restrict__ AL,
       const uint4* __restrict__ Wf,
       __nv_bfloat16* __restrict__ yB, float* __restrict__ z) {
    extern __shared__ __align__(16) __nv_bfloat16 sA[];   // [chunk][plane][SA_CHUNK]
    int tid = threadIdx.x;
    int wid = tid >> 5, lane = tid & 31;
    int m0 = blockIdx.x * 128;
    int wm = wid & 3, wn = wid >> 2;
    int jbase = blockIdx.y * 16;

    float acc[2][8][4];
#pragma unroll
    for (int a = 0; a < 2; a++)
#pragma unroll
        for (int b = 0; b < 8; b++)
#pragma unroll
            for (int q = 0; q < 4; q++) acc[a][b][q] = 0.f;

    int frow = tid >> 1, fhalf = tid & 1;   // plane pad rows are zero -> no guard
    int g = lane >> 3, ri = lane & 7;
    uint32_t sbase = smem_to_u32(sA);

    // ---- issue both chunks' async copies up front ----
#pragma unroll
    for (int c = 0; c < 2; c++) {
#pragma unroll
        for (int p = 0; p < 2; p++) {
            const __nv_bfloat16* gsrc =
                (p ? AL : AH) + (size_t)(m0 + frow) * DD + c * 64 + fhalf * 32;
            uint32_t sdst = sbase + (uint32_t)((c * 2 + p) * SA_CHUNK
                                               + frow * SA_STRIDE + fhalf * 32) * 2;
#pragma unroll
            for (int q = 0; q < 4; q++)
                CP_ASYNC16(sdst + q * 16, (const char*)(gsrc + q * 8));
        }
        CP_COMMIT();
    }

#pragma unroll 1
    for (int c = 0; c < 2; c++) {
        if (c == 0) CP_WAIT(1); else CP_WAIT(0);
        __syncthreads();
        uint32_t sAh_u = sbase + (uint32_t)(c * 2 + 0) * SA_CHUNK * 2;
        uint32_t sAl_u = sbase + (uint32_t)(c * 2 + 1) * SA_CHUNK * 2;

#pragma unroll
        for (int ss = 0; ss < 4; ss++) {
            int s = c * 4 + ss;
            int k0 = ss * 16;
            uint32_t Ah[2][4], Al[2][4];
#pragma unroll
            for (int mt = 0; mt < 2; mt++) {
                uint32_t row = (uint32_t)(wm * 32 + mt * 16 + (g & 1) * 8 + ri);
                uint32_t byo = (row * SA_STRIDE + (uint32_t)(k0 + (g >> 1) * 8)) * 2;
                LDM_X4(Ah[mt], sAh_u + byo);
                LDM_X4(Al[mt], sAl_u + byo);
            }
#pragma unroll
            for (int nt = 0; nt < 8; nt++) {
                int j = jbase + wn * 8 + nt;
                uint4 wv = __ldg(&Wf[((j * 8 + s) << 5) + lane]);
                MMA_BF16(acc[0][nt], wv.x, wv.y, Ah[0]);
                MMA_BF16(acc[1][nt], wv.x, wv.y, Ah[1]);
                MMA_BF16(acc[0][nt], wv.x, wv.y, Al[0]);
                MMA_BF16(acc[1][nt], wv.x, wv.y, Al[1]);
                MMA_BF16(acc[0][nt], wv.z, wv.w, Ah[0]);
                MMA_BF16(acc[1][nt], wv.z, wv.w, Ah[1]);
            }
        }
    }

    // epilogue: y-half (blockIdx.y==0) -> bf16, z-half -> fp32; no bias
    int r_in = lane >> 2;
    int n_in = (lane & 3) * 2;
    bool isY = (blockIdx.y == 0);
#pragma unroll
    for (int nt = 0; nt < 8; nt++) {
        int n = wn * 64 + nt * 8 + n_in;   // 0..127 within half
#pragma unroll
        for (int mt = 0; mt < 2; mt++) {
            int r0 = m0 + wm * 32 + mt * 16 + r_in;
            if (r0 < NN) {
                if (isY) {
                    __nv_bfloat162 o = __floats2bfloat162_rn(acc[mt][nt][0], acc[mt][nt][1]);
                    *(uint32_t*)(yB + (size_t)r0 * DD + n) = bf2u(o);
                } else {
                    *(float2*)(z + (size_t)r0 * DD + n) = make_float2(acc[mt][nt][0], acc[mt][nt][1]);
                }
            }
            int r1 = r0 + 8;
            if (r1 < NN) {
                if (isY) {
                    __nv_bfloat162 o = __floats2bfloat162_rn(acc[mt][nt][2], acc[mt][nt][3]);
                    *(uint32_t*)(yB + (size_t)r1 * DD + n) = bf2u(o);
                } else {
                    *(float2*)(z + (size_t)r1 * DD + n) = make_float2(acc[mt][nt][2], acc[mt][nt][3]);
                }
            }
        }
    }
}

// ---------------- fused agg + epilogue: h = relu(mean_nb(Y) + Z + bias) ----------
__global__ void k_aggf(const float* __restrict__ z, const float* __restrict__ bias,
                       __nv_bfloat16* __restrict__ outH, __nv_bfloat16* __restrict__ outL,
                       float* __restrict__ outF) {
    int w = (blockIdx.x * blockDim.x + threadIdx.x) >> 5;
    int lane = threadIdx.x & 31;
    if (w >= NN) return;
    int beg = g_rowptr[w];
    int dcnt = g_deg[w];
    int end = beg + dcnt;
    const uint2* in2 = (const uint2*)g_yB;
    float a0 = 0.f, a1 = 0.f, a2 = 0.f, a3 = 0.f;
    int e = beg;
#pragma unroll 1
    for (; e + 7 < end; e += 8) {
        int s0 = __ldg(&g_esrc[e]);
        int s1 = __ldg(&g_esrc[e + 1]);
        int s2 = __ldg(&g_esrc[e + 2]);
        int s3 = __ldg(&g_esrc[e + 3]);
        int s4 = __ldg(&g_esrc[e + 4]);
        int s5 = __ldg(&g_esrc[e + 5]);
        int s6 = __ldg(&g_esrc[e + 6]);
        int s7 = __ldg(&g_esrc[e + 7]);
        uint2 v0 = __ldg(&in2[(size_t)s0 * 32 + lane]);
        uint2 v1 = __ldg(&in2[(size_t)s1 * 32 + lane]);
        uint2 v2 = __ldg(&in2[(size_t)s2 * 32 + lane]);
        uint2 v3 = __ldg(&in2[(size_t)s3 * 32 + lane]);
        uint2 v4 = __ldg(&in2[(size_t)s4 * 32 + lane]);
        uint2 v5 = __ldg(&in2[(size_t)s5 * 32 + lane]);
        uint2 v6 = __ldg(&in2[(size_t)s6 * 32 + lane]);
        uint2 v7 = __ldg(&in2[(size_t)s7 * 32 + lane]);
#pragma unroll
        for (int q = 0; q < 8; q++) {
            uint2 v = q == 0 ? v0 : q == 1 ? v1 : q == 2 ? v2 : q == 3 ? v3
                    : q == 4 ? v4 : q == 5 ? v5 : q == 6 ? v6 : v7;
            float2 p0 = __bfloat1622float2(*(__nv_bfloat162*)&v.x);
            float2 p1 = __bfloat1622float2(*(__nv_bfloat162*)&v.y);
            a0 += p0.x; a1 += p0.y; a2 += p1.x; a3 += p1.y;
        }
    }
    for (; e < end; e++) {
        int s0 = __ldg(&g_esrc[e]);
        uint2 v = __ldg(&in2[(size_t)s0 * 32 + lane]);
        float2 p0 = __bfloat1622float2(*(__nv_bfloat162*)&v.x);
        float2 p1 = __bfloat1622float2(*(__nv_bfloat162*)&v.y);
        a0 += p0.x; a1 += p0.y; a2 += p1.x; a3 += p1.y;
    }
    float inv = (dcnt > 0) ? 1.0f / (float)dcnt : 0.0f;
    float4 zz = ((const float4*)z)[w * 32 + lane];
    float4 bb = ((const float4*)bias)[lane];
    float f0 = fmaxf(a0 * inv + zz.x + bb.x, 0.f);
    float f1 = fmaxf(a1 * inv + zz.y + bb.y, 0.f);
    float f2 = fmaxf(a2 * inv + zz.z + bb.z, 0.f);
    float f3 = fmaxf(a3 * inv + zz.w + bb.w, 0.f);
    if (outF) {
        ((float4*)outF)[w * 32 + lane] = make_float4(f0, f1, f2, f3);
    } else {
        __nv_bfloat162 h01 = __floats2bfloat162_rn(f0, f1);
        __nv_bfloat162 h23 = __floats2bfloat162_rn(f2, f3);
        __nv_bfloat162 l01 = __floats2bfloat162_rn(f0 - __bfloat162float(h01.x),
                                                   f1 - __bfloat162float(h01.y));
        __nv_bfloat162 l23 = __floats2bfloat162_rn(f2 - __bfloat162float(h23.x),
                                                   f3 - __bfloat162float(h23.y));
        ((uint2*)outH)[w * 32 + lane] = make_uint2(bf2u(h01), bf2u(h23));
        ((uint2*)outL)[w * 32 + lane] = make_uint2(bf2u(l01), bf2u(l23));
    }
}

// ---------------- global add pool (batch is sorted, int32) ----------------
#define NPB 256
__global__ void k_pool(const float* __restrict__ h, const int* __restrict__ batch) {
    int t = threadIdx.x;
    int start = blockIdx.x * NPB;
    int end = start + NPB; if (end > NN) end = NN;
    if (start >= NN) return;
    int cur = batch[start];
    float sum = 0.f;
    for (int i = start; i < end; i++) {
        int b = __ldg(&batch[i]);
        if (b != cur) {
            atomicAdd(&g_pool[cur * DD + t], sum);
            sum = 0.f; cur = b;
        }
        sum += h[(size_t)i * DD + t];
    }
    atomicAdd(&g_pool[cur * DD + t], sum);
}

// ---------------- LayerNorm + final linear + scratch re-zero ----------------
__global__ void k_final(const float* __restrict__ ln_g, const float* __restrict__ ln_b,
                        const float* __restrict__ Wlin, const float* __restrict__ blin,
                        float* __restrict__ out) {
    int gtid = blockIdx.x * blockDim.x + threadIdx.x;
    int w = gtid >> 5;
    int lane = threadIdx.x & 31;
    if (w < NG) {
        float4 v = ((const float4*)g_pool)[w * 32 + lane];
        float s = v.x + v.y + v.z + v.w;
#pragma unroll
        for (int o = 16; o; o >>= 1) s += __shfl_xor_sync(0xffffffffu, s, o);
        float mean = s * (1.0f / 128.0f);
        float dx = v.x - mean, dy = v.y - mean, dz = v.z - mean, dw = v.w - mean;
        float q = dx * dx + dy * dy + dz * dz + dw * dw;
#pragma unroll
        for (int o = 16; o; o >>= 1) q += __shfl_xor_sync(0xffffffffu, q, o);
        float var = q * (1.0f / 128.0f);
        float r = rsqrtf(var + 1e-5f);
        float4 gg = ((const float4*)ln_g)[lane];
        float4 bb = ((const float4*)ln_b)[lane];
        float n0 = dx * r * gg.x + bb.x;
        float n1 = dy * r * gg.y + bb.y;
        float n2 = dz * r * gg.z + bb.z;
        float n3 = dw * r * gg.w + bb.w;
        float4 w0 = ((const float4*)Wlin)[lane];
        float4 w1 = ((const float4*)Wlin)[32 + lane];
        float d0 = n0 * w0.x + n1 * w0.y + n2 * w0.z + n3 * w0.w;
        float d1 = n0 * w1.x + n1 * w1.y + n2 * w1.z + n3 * w1.w;
#pragma unroll
        for (int o = 16; o; o >>= 1) {
            d0 += __shfl_xor_sync(0xffffffffu, d0, o);
            d1 += __shfl_xor_sync(0xffffffffu, d1, o);
        }
        if (lane == 0) {
            out[w * 2 + 0] = d0 + blin[0];
            out[w * 2 + 1] = d1 + blin[1];
        }
        ((float4*)g_pool)[w * 32 + lane] = make_float4(0.f, 0.f, 0.f, 0.f);
    }
    if (gtid == 0) g_alloc = 0;
    for (int i = gtid; i < NN; i += NG * 32) { g_deg[i] = 0; g_cursor[i] = 0; }
}

// ---------------- launch ----------------
extern "C" void kernel_launch(void* const* d_in, const int* in_sizes, int n_in,
                              void* d_out, int out_size) {
    const float* x     = (const float*)d_in[0];
    const int*   ei    = (const int*)d_in[1];
    const int*   bat   = (const int*)d_in[2];
    const float* W1l   = (const float*)d_in[3];
    const float* b1l   = (const float*)d_in[4];
    const float* W1r   = (const float*)d_in[5];
    const float* W2l   = (const float*)d_in[6];
    const float* b2l   = (const float*)d_in[7];
    const float* W2r   = (const float*)d_in[8];
    const float* ln_g  = (const float*)d_in[9];
    const float* ln_b  = (const float*)d_in[10];
    const float* Wlin  = (const float*)d_in[11];
    const float* blin  = (const float*)d_in[12];

    const int* src = ei;
    const int* dst = ei + NE;

    __nv_bfloat16 *xH, *xL, *hH, *hL, *yB;
    float *z, *h2;
    uint4* wf;
    cudaGetSymbolAddress((void**)&xH, g_xH);
    cudaGetSymbolAddress((void**)&xL, g_xL);
    cudaGetSymbolAddress((void**)&hH, g_hH);
    cudaGetSymbolAddress((void**)&hL, g_hL);
    cudaGetSymbolAddress((void**)&yB, g_yB);
    cudaGetSymbolAddress((void**)&z,  g_z);
    cudaGetSymbolAddress((void**)&h2, g_h2);
    cudaGetSymbolAddress((void**)&wf, g_Wf);

    cudaFuncSetAttribute(k_gemm, cudaFuncAttributeMaxDynamicSharedMemorySize, SMEM_GEMM);

    int degblks = (NE + 255) / 256;
    k_prep_deg<<<PREP_XB_BLKS + PREP_WF_BLKS + degblks, 256>>>(x, W1l, W1r, W2l, W2r, dst);  // 0
    k_alloc<<<NB_SCAN, 256>>>();                                                              // 1
    k_scatter<<<degblks, 256>>>(src, dst);                                                    // 2

    const int LSTRIDE = 32 * 8 * 32;   // uint4 per layer
    dim3 ggrid((NN + 127) / 128, 2);
    k_gemm<<<ggrid, 256, SMEM_GEMM>>>(xH, xL, wf, yB, z);                                     // 3 (profiled)
    k_aggf<<<(NN * 32 + 255) / 256, 256>>>(z, b1l, hH, hL, (float*)nullptr);                  // 4
    k_gemm<<<ggrid, 256, SMEM_GEMM>>>(hH, hL, wf + LSTRIDE, yB, z);                           // 5
    k_aggf<<<(NN * 32 + 255) / 256, 256>>>(z, b2l, (__nv_bfloat16*)nullptr,
                                           (__nv_bfloat16*)nullptr, h2);                      // 6

    k_pool<<<(NN + NPB - 1) / NPB, 128>>>(h2, bat);                                           // 7
    k_final<<<(NG * 32 + 255) / 256, 256>>>(ln_g, ln_b, Wlin, blin, (float*)d_out);           // 8
}

// round 13
// speedup vs baseline: 1.2226x; 1.0412x over previous
#include <cuda_runtime.h>
#include <cuda_bf16.h>
#include <cstdint>

#define NN 100000
#define NPAD 100096   // 782*128, pad rows stay zero forever
#define NE 1600000
#define NG 1024
#define DD 128
#define NB_SCAN 391   // ceil(NN/256)

// ---------------- scratch (device globals; zero-initialized at load; k_final's
// tail re-zeros deg/cursor/alloc/pool; plane pad rows are never written) -------
__device__ __nv_bfloat16 g_xH[NPAD * DD];
__device__ __nv_bfloat16 g_xL[NPAD * DD];
__device__ __nv_bfloat16 g_hH[NPAD * DD];   // h1 hi plane (gemm2 A)
__device__ __nv_bfloat16 g_hL[NPAD * DD];
__device__ __nv_bfloat16 g_yB[NPAD * DD];   // Y = src@Wl^T, bf16 (gather source)
__device__ float g_z[NN * DD];              // Z = src@Wr^T, fp32
__device__ float g_h2[NN * DD];
__device__ float g_pool[NG * DD];
// W frags interleaved: [layer][j 0..31][s 0..7][lane] -> uint4 {bh01,bh23,bl01,bl23}
__device__ uint4 g_Wf[2 * 32 * 8 * 32];
__device__ int   g_deg[NN];
__device__ int   g_rowptr[NN];
__device__ int   g_cursor[NN];
__device__ int   g_esrc[NE];
__device__ int   g_alloc;

// ---------------- helpers ----------------
__device__ __forceinline__ uint32_t smem_to_u32(const void* p) {
    uint32_t a;
    asm("{ .reg .u64 t; cvta.to.shared.u64 t, %1; cvt.u32.u64 %0, t; }" : "=r"(a) : "l"(p));
    return a;
}
__device__ __forceinline__ uint32_t bf2u(__nv_bfloat162 v) { return *reinterpret_cast<uint32_t*>(&v); }

#define LDM_X4(r, addr) \
    asm volatile("ldmatrix.sync.aligned.m8n8.x4.shared.b16 {%0,%1,%2,%3}, [%4];" \
        : "=r"((r)[0]), "=r"((r)[1]), "=r"((r)[2]), "=r"((r)[3]) : "r"(addr))

#define MMA_BF16(c, b0, b1, a) \
    asm volatile("mma.sync.aligned.m16n8k16.row.col.f32.bf16.bf16.f32 " \
        "{%0,%1,%2,%3}, {%4,%5,%6,%7}, {%8,%9}, {%0,%1,%2,%3};" \
        : "+f"((c)[0]), "+f"((c)[1]), "+f"((c)[2]), "+f"((c)[3]) \
        : "r"((a)[0]), "r"((a)[1]), "r"((a)[2]), "r"((a)[3]), "r"(b0), "r"(b1))

#define CP_ASYNC16(dst, src) \
    asm volatile("cp.async.cg.shared.global [%0], [%1], 16;" :: "r"(dst), "l"(src))
#define CP_COMMIT() asm volatile("cp.async.commit_group;" ::: "memory")
#define CP_WAIT(n)  asm volatile("cp.async.wait_group %0;" :: "n"(n) : "memory")

// ---------------- slot 0: prep (x->hi/lo planes, W frag interleave) + degree ----
#define PREP_XB_BLKS 12500   // NN*DD/4 / 256
#define PREP_WF_BLKS 64      // 2*32*8*32 / 256
__global__ void k_prep_deg(const float* __restrict__ x,
                           const float* __restrict__ W1l, const float* __restrict__ W1r,
                           const float* __restrict__ W2l, const float* __restrict__ W2r,
                           const int* __restrict__ dst) {
    if (blockIdx.x < PREP_XB_BLKS) {
        int i = blockIdx.x * 256 + threadIdx.x;
        float4 f = ((const float4*)x)[i];
        __nv_bfloat162 h01 = __floats2bfloat162_rn(f.x, f.y);
        __nv_bfloat162 h23 = __floats2bfloat162_rn(f.z, f.w);
        __nv_bfloat162 l01 = __floats2bfloat162_rn(f.x - __bfloat162float(h01.x),
                                                   f.y - __bfloat162float(h01.y));
        __nv_bfloat162 l23 = __floats2bfloat162_rn(f.z - __bfloat162float(h23.x),
                                                   f.w - __bfloat162float(h23.y));
        ((uint2*)g_xH)[i] = make_uint2(bf2u(h01), bf2u(h23));
        ((uint2*)g_xL)[i] = make_uint2(bf2u(l01), bf2u(l23));
        return;
    }
    if (blockIdx.x < PREP_XB_BLKS + PREP_WF_BLKS) {
        int i = (blockIdx.x - PREP_XB_BLKS) * 256 + threadIdx.x;   // 0 .. 16383
        int lane = i & 31;
        int s = (i >> 5) & 7;         // k-step 0..7 (K=128)
        int j = (i >> 8) & 31;        // n-tile 0..31 (N=256: j<16 -> Wl, else Wr)
        int layer = i >> 13;
        int n = (j & 15) * 8 + (lane >> 2);
        int k = s * 16 + (lane & 3) * 2;
        const float* Wl = layer ? W2l : W1l;
        const float* Wr = layer ? W2r : W1r;
        const float* W = (j < 16) ? Wl : Wr;
        float w[4];
#pragma unroll
        for (int q = 0; q < 4; q++) {
            int kk = k + (q >> 1) * 8 + (q & 1);
            w[q] = W[n * DD + kk];
        }
        __nv_bfloat16 h[4], l[4];
#pragma unroll
        for (int q = 0; q < 4; q++) {
            h[q] = __float2bfloat16(w[q]);
            l[q] = __float2bfloat16(w[q] - __bfloat162float(h[q]));
        }
        __nv_bfloat162 h01; h01.x = h[0]; h01.y = h[1];
        __nv_bfloat162 h23; h23.x = h[2]; h23.y = h[3];
        __nv_bfloat162 l01; l01.x = l[0]; l01.y = l[1];
        __nv_bfloat162 l23; l23.x = l[2]; l23.y = l[3];
        g_Wf[i] = make_uint4(bf2u(h01), bf2u(h23), bf2u(l01), bf2u(l23));
        return;
    }
    int i = (blockIdx.x - PREP_XB_BLKS - PREP_WF_BLKS) * 256 + threadIdx.x;
    if (i < NE) atomicAdd(&g_deg[dst[i]], 1);
}

// ---------------- slot 1: bucket allocation ----------------
__global__ void k_alloc() {
    __shared__ int s[256];
    __shared__ int base;
    int b = blockIdx.x, t = threadIdx.x;
    int i = b * 256 + t;
    int v = (i < NN) ? g_deg[i] : 0;
    s[t] = v;
    __syncthreads();
#pragma unroll
    for (int off = 1; off < 256; off <<= 1) {
        int add = (t >= off) ? s[t - off] : 0;
        __syncthreads();
        s[t] += add;
        __syncthreads();
    }
    if (t == 255) base = atomicAdd(&g_alloc, s[255]);
    __syncthreads();
    if (i < NN) g_rowptr[i] = base + s[t] - v;
}

// ---------------- slot 2: scatter edges into buckets ----------------
__global__ void k_scatter(const int* __restrict__ src, const int* __restrict__ dst) {
    int i = blockIdx.x * blockDim.x + threadIdx.x;
    if (i >= NE) return;
    int d = dst[i];
    int pos = atomicAdd(&g_cursor[d], 1);
    g_esrc[g_rowptr[d] + pos] = src[i];
}

// ---------------- slot 3 (PROFILED): GEMM  [Y|Z] = A @ [Wl;Wr]^T ----------------
// cp.async double-buffered A; MMA inner loop reordered: W frags for 4 n-tiles are
// register-hoisted, split-terms run as outer passes -> consecutive MMAs hit
// DIFFERENT accumulators (dependency distance 8 issues instead of 1).
#define SA_STRIDE 72
#define SA_CHUNK (128 * SA_STRIDE)                 // bf16 elems per plane-chunk
#define SMEM_GEMM (4 * SA_CHUNK * 2)               // 2 chunks x 2 planes, bytes
__global__ void __launch_bounds__(256, 2)
k_gemm(const __nv_bfloat16* __restrict__ AH, const __nv_bfloat16* __restrict__ AL,
       const uint4* __restrict__ Wf,
       __nv_bfloat16* __restrict__ yB, float* __restrict__ z) {
    extern __shared__ __align__(16) __nv_bfloat16 sA[];   // [chunk][plane][SA_CHUNK]
    int tid = threadIdx.x;
    int wid = tid >> 5, lane = tid & 31;
    int m0 = blockIdx.x * 128;
    int wm = wid & 3, wn = wid >> 2;
    int jbase = blockIdx.y * 16;

    float acc[2][8][4];
#pragma unroll
    for (int a = 0; a < 2; a++)
#pragma unroll
        for (int b = 0; b < 8; b++)
#pragma unroll
            for (int q = 0; q < 4; q++) acc[a][b][q] = 0.f;

    int frow = tid >> 1, fhalf = tid & 1;   // plane pad rows are zero -> no guard
    int g = lane >> 3, ri = lane & 7;
    uint32_t sbase = smem_to_u32(sA);

    // ---- issue both chunks' async copies up front ----
#pragma unroll
    for (int c = 0; c < 2; c++) {
#pragma unroll
        for (int p = 0; p < 2; p++) {
            const __nv_bfloat16* gsrc =
                (p ? AL : AH) + (size_t)(m0 + frow) * DD + c * 64 + fhalf * 32;
            uint32_t sdst = sbase + (uint32_t)((c * 2 + p) * SA_CHUNK
                                               + frow * SA_STRIDE + fhalf * 32) * 2;
#pragma unroll
            for (int q = 0; q < 4; q++)
                CP_ASYNC16(sdst + q * 16, (const char*)(gsrc + q * 8));
        }
        CP_COMMIT();
    }

#pragma unroll 1
    for (int c = 0; c < 2; c++) {
        if (c == 0) CP_WAIT(1); else CP_WAIT(0);
        __syncthreads();
        uint32_t sAh_u = sbase + (uint32_t)(c * 2 + 0) * SA_CHUNK * 2;
        uint32_t sAl_u = sbase + (uint32_t)(c * 2 + 1) * SA_CHUNK * 2;

#pragma unroll
        for (int ss = 0; ss < 4; ss++) {
            int s = c * 4 + ss;
            int k0 = ss * 16;
            uint32_t Ah[2][4], Al[2][4];
#pragma unroll
            for (int mt = 0; mt < 2; mt++) {
                uint32_t row = (uint32_t)(wm * 32 + mt * 16 + (g & 1) * 8 + ri);
                uint32_t byo = (row * SA_STRIDE + (uint32_t)(k0 + (g >> 1) * 8)) * 2;
                LDM_X4(Ah[mt], sAh_u + byo);
                LDM_X4(Al[mt], sAl_u + byo);
            }
            // process n-tiles in groups of 4: hoist W, then 3 term-passes
#pragma unroll
            for (int g4 = 0; g4 < 2; g4++) {
                uint4 wv[4];
#pragma unroll
                for (int q = 0; q < 4; q++) {
                    int j = jbase + wn * 8 + g4 * 4 + q;
                    wv[q] = __ldg(&Wf[((j * 8 + s) << 5) + lane]);
                }
                // pass 1: Ah * Wh  (8 independent MMAs)
#pragma unroll
                for (int q = 0; q < 4; q++) {
                    int nt = g4 * 4 + q;
                    MMA_BF16(acc[0][nt], wv[q].x, wv[q].y, Ah[0]);
                    MMA_BF16(acc[1][nt], wv[q].x, wv[q].y, Ah[1]);
                }
                // pass 2: Al * Wh
#pragma unroll
                for (int q = 0; q < 4; q++) {
                    int nt = g4 * 4 + q;
                    MMA_BF16(acc[0][nt], wv[q].x, wv[q].y, Al[0]);
                    MMA_BF16(acc[1][nt], wv[q].x, wv[q].y, Al[1]);
                }
                // pass 3: Ah * Wl
#pragma unroll
                for (int q = 0; q < 4; q++) {
                    int nt = g4 * 4 + q;
                    MMA_BF16(acc[0][nt], wv[q].z, wv[q].w, Ah[0]);
                    MMA_BF16(acc[1][nt], wv[q].z, wv[q].w, Ah[1]);
                }
            }
        }
    }

    // epilogue: y-half (blockIdx.y==0) -> bf16, z-half -> fp32; no bias
    int r_in = lane >> 2;
    int n_in = (lane & 3) * 2;
    bool isY = (blockIdx.y == 0);
#pragma unroll
    for (int nt = 0; nt < 8; nt++) {
        int n = wn * 64 + nt * 8 + n_in;   // 0..127 within half
#pragma unroll
        for (int mt = 0; mt < 2; mt++) {
            int r0 = m0 + wm * 32 + mt * 16 + r_in;
            if (r0 < NN) {
                if (isY) {
                    __nv_bfloat162 o = __floats2bfloat162_rn(acc[mt][nt][0], acc[mt][nt][1]);
                    *(uint32_t*)(yB + (size_t)r0 * DD + n) = bf2u(o);
                } else {
                    *(float2*)(z + (size_t)r0 * DD + n) = make_float2(acc[mt][nt][0], acc[mt][nt][1]);
                }
            }
            int r1 = r0 + 8;
            if (r1 < NN) {
                if (isY) {
                    __nv_bfloat162 o = __floats2bfloat162_rn(acc[mt][nt][2], acc[mt][nt][3]);
                    *(uint32_t*)(yB + (size_t)r1 * DD + n) = bf2u(o);
                } else {
                    *(float2*)(z + (size_t)r1 * DD + n) = make_float2(acc[mt][nt][2], acc[mt][nt][3]);
                }
            }
        }
    }
}

// ---------------- fused agg + epilogue: h = relu(mean_nb(Y) + Z + bias) ----------
__global__ void k_aggf(const float* __restrict__ z, const float* __restrict__ bias,
                       __nv_bfloat16* __restrict__ outH, __nv_bfloat16* __restrict__ outL,
                       float* __restrict__ outF) {
    int w = (blockIdx.x * blockDim.x + threadIdx.x) >> 5;
    int lane = threadIdx.x & 31;
    if (w >= NN) return;
    int beg = g_rowptr[w];
    int dcnt = g_deg[w];
    int end = beg + dcnt;
    const uint2* in2 = (const uint2*)g_yB;
    float a0 = 0.f, a1 = 0.f, a2 = 0.f, a3 = 0.f;
    int e = beg;
#pragma unroll 1
    for (; e + 7 < end; e += 8) {
        int s0 = __ldg(&g_esrc[e]);
        int s1 = __ldg(&g_esrc[e + 1]);
        int s2 = __ldg(&g_esrc[e + 2]);
        int s3 = __ldg(&g_esrc[e + 3]);
        int s4 = __ldg(&g_esrc[e + 4]);
        int s5 = __ldg(&g_esrc[e + 5]);
        int s6 = __ldg(&g_esrc[e + 6]);
        int s7 = __ldg(&g_esrc[e + 7]);
        uint2 v0 = __ldg(&in2[(size_t)s0 * 32 + lane]);
        uint2 v1 = __ldg(&in2[(size_t)s1 * 32 + lane]);
        uint2 v2 = __ldg(&in2[(size_t)s2 * 32 + lane]);
        uint2 v3 = __ldg(&in2[(size_t)s3 * 32 + lane]);
        uint2 v4 = __ldg(&in2[(size_t)s4 * 32 + lane]);
        uint2 v5 = __ldg(&in2[(size_t)s5 * 32 + lane]);
        uint2 v6 = __ldg(&in2[(size_t)s6 * 32 + lane]);
        uint2 v7 = __ldg(&in2[(size_t)s7 * 32 + lane]);
#pragma unroll
        for (int q = 0; q < 8; q++) {
            uint2 v = q == 0 ? v0 : q == 1 ? v1 : q == 2 ? v2 : q == 3 ? v3
                    : q == 4 ? v4 : q == 5 ? v5 : q == 6 ? v6 : v7;
            float2 p0 = __bfloat1622float2(*(__nv_bfloat162*)&v.x);
            float2 p1 = __bfloat1622float2(*(__nv_bfloat162*)&v.y);
            a0 += p0.x; a1 += p0.y; a2 += p1.x; a3 += p1.y;
        }
    }
    for (; e < end; e++) {
        int s0 = __ldg(&g_esrc[e]);
        uint2 v = __ldg(&in2[(size_t)s0 * 32 + lane]);
        float2 p0 = __bfloat1622float2(*(__nv_bfloat162*)&v.x);
        float2 p1 = __bfloat1622float2(*(__nv_bfloat162*)&v.y);
        a0 += p0.x; a1 += p0.y; a2 += p1.x; a3 += p1.y;
    }
    float inv = (dcnt > 0) ? 1.0f / (float)dcnt : 0.0f;
    float4 zz = ((const float4*)z)[w * 32 + lane];
    float4 bb = ((const float4*)bias)[lane];
    float f0 = fmaxf(a0 * inv + zz.x + bb.x, 0.f);
    float f1 = fmaxf(a1 * inv + zz.y + bb.y, 0.f);
    float f2 = fmaxf(a2 * inv + zz.z + bb.z, 0.f);
    float f3 = fmaxf(a3 * inv + zz.w + bb.w, 0.f);
    if (outF) {
        ((float4*)outF)[w * 32 + lane] = make_float4(f0, f1, f2, f3);
    } else {
        __nv_bfloat162 h01 = __floats2bfloat162_rn(f0, f1);
        __nv_bfloat162 h23 = __floats2bfloat162_rn(f2, f3);
        __nv_bfloat162 l01 = __floats2bfloat162_rn(f0 - __bfloat162float(h01.x),
                                                   f1 - __bfloat162float(h01.y));
        __nv_bfloat162 l23 = __floats2bfloat162_rn(f2 - __bfloat162float(h23.x),
                                                   f3 - __bfloat162float(h23.y));
        ((uint2*)outH)[w * 32 + lane] = make_uint2(bf2u(h01), bf2u(h23));
        ((uint2*)outL)[w * 32 + lane] = make_uint2(bf2u(l01), bf2u(l23));
    }
}

// ---------------- global add pool (batch is sorted, int32) ----------------
#define NPB 256
__global__ void k_pool(const float* __restrict__ h, const int* __restrict__ batch) {
    int t = threadIdx.x;
    int start = blockIdx.x * NPB;
    int end = start + NPB; if (end > NN) end = NN;
    if (start >= NN) return;
    int cur = batch[start];
    float sum = 0.f;
    for (int i = start; i < end; i++) {
        int b = __ldg(&batch[i]);
        if (b != cur) {
            atomicAdd(&g_pool[cur * DD + t], sum);
            sum = 0.f; cur = b;
        }
        sum += h[(size_t)i * DD + t];
    }
    atomicAdd(&g_pool[cur * DD + t], sum);
}

// ---------------- LayerNorm + final linear + scratch re-zero ----------------
__global__ void k_final(const float* __restrict__ ln_g, const float* __restrict__ ln_b,
                        const float* __restrict__ Wlin, const float* __restrict__ blin,
                        float* __restrict__ out) {
    int gtid = blockIdx.x * blockDim.x + threadIdx.x;
    int w = gtid >> 5;
    int lane = threadIdx.x & 31;
    if (w < NG) {
        float4 v = ((const float4*)g_pool)[w * 32 + lane];
        float s = v.x + v.y + v.z + v.w;
#pragma unroll
        for (int o = 16; o; o >>= 1) s += __shfl_xor_sync(0xffffffffu, s, o);
        float mean = s * (1.0f / 128.0f);
        float dx = v.x - mean, dy = v.y - mean, dz = v.z - mean, dw = v.w - mean;
        float q = dx * dx + dy * dy + dz * dz + dw * dw;
#pragma unroll
        for (int o = 16; o; o >>= 1) q += __shfl_xor_sync(0xffffffffu, q, o);
        float var = q * (1.0f / 128.0f);
        float r = rsqrtf(var + 1e-5f);
        float4 gg = ((const float4*)ln_g)[lane];
        float4 bb = ((const float4*)ln_b)[lane];
        float n0 = dx * r * gg.x + bb.x;
        float n1 = dy * r * gg.y + bb.y;
        float n2 = dz * r * gg.z + bb.z;
        float n3 = dw * r * gg.w + bb.w;
        float4 w0 = ((const float4*)Wlin)[lane];
        float4 w1 = ((const float4*)Wlin)[32 + lane];
        float d0 = n0 * w0.x + n1 * w0.y + n2 * w0.z + n3 * w0.w;
        float d1 = n0 * w1.x + n1 * w1.y + n2 * w1.z + n3 * w1.w;
#pragma unroll
        for (int o = 16; o; o >>= 1) {
            d0 += __shfl_xor_sync(0xffffffffu, d0, o);
            d1 += __shfl_xor_sync(0xffffffffu, d1, o);
        }
        if (lane == 0) {
            out[w * 2 + 0] = d0 + blin[0];
            out[w * 2 + 1] = d1 + blin[1];
        }
        ((float4*)g_pool)[w * 32 + lane] = make_float4(0.f, 0.f, 0.f, 0.f);
    }
    if (gtid == 0) g_alloc = 0;
    for (int i = gtid; i < NN; i += NG * 32) { g_deg[i] = 0; g_cursor[i] = 0; }
}

// ---------------- launch ----------------
extern "C" void kernel_launch(void* const* d_in, const int* in_sizes, int n_in,
                              void* d_out, int out_size) {
    const float* x     = (const float*)d_in[0];
    const int*   ei    = (const int*)d_in[1];
    const int*   bat   = (const int*)d_in[2];
    const float* W1l   = (const float*)d_in[3];
    const float* b1l   = (const float*)d_in[4];
    const float* W1r   = (const float*)d_in[5];
    const float* W2l   = (const float*)d_in[6];
    const float* b2l   = (const float*)d_in[7];
    const float* W2r   = (const float*)d_in[8];
    const float* ln_g  = (const float*)d_in[9];
    const float* ln_b  = (const float*)d_in[10];
    const float* Wlin  = (const float*)d_in[11];
    const float* blin  = (const float*)d_in[12];

    const int* src = ei;
    const int* dst = ei + NE;

    __nv_bfloat16 *xH, *xL, *hH, *hL, *yB;
    float *z, *h2;
    uint4* wf;
    cudaGetSymbolAddress((void**)&xH, g_xH);
    cudaGetSymbolAddress((void**)&xL, g_xL);
    cudaGetSymbolAddress((void**)&hH, g_hH);
    cudaGetSymbolAddress((void**)&hL, g_hL);
    cudaGetSymbolAddress((void**)&yB, g_yB);
    cudaGetSymbolAddress((void**)&z,  g_z);
    cudaGetSymbolAddress((void**)&h2, g_h2);
    cudaGetSymbolAddress((void**)&wf, g_Wf);

    cudaFuncSetAttribute(k_gemm, cudaFuncAttributeMaxDynamicSharedMemorySize, SMEM_GEMM);

    int degblks = (NE + 255) / 256;
    k_prep_deg<<<PREP_XB_BLKS + PREP_WF_BLKS + degblks, 256>>>(x, W1l, W1r, W2l, W2r, dst);  // 0
    k_alloc<<<NB_SCAN, 256>>>();                                                              // 1
    k_scatter<<<degblks, 256>>>(src, dst);                                                    // 2

    const int LSTRIDE = 32 * 8 * 32;   // uint4 per layer
    dim3 ggrid((NN + 127) / 128, 2);
    k_gemm<<<ggrid, 256, SMEM_GEMM>>>(xH, xL, wf, yB, z);                                     // 3 (profiled)
    k_aggf<<<(NN * 32 + 255) / 256, 256>>>(z, b1l, hH, hL, (float*)nullptr);                  // 4
    k_gemm<<<ggrid, 256, SMEM_GEMM>>>(hH, hL, wf + LSTRIDE, yB, z);                           // 5
    k_aggf<<<(NN * 32 + 255) / 256, 256>>>(z, b2l, (__nv_bfloat16*)nullptr,
                                           (__nv_bfloat16*)nullptr, h2);                      // 6

    k_pool<<<(NN + NPB - 1) / NPB, 128>>>(h2, bat);                                           // 7
    k_final<<<(NG * 32 + 255) / 256, 256>>>(ln_g, ln_b, Wlin, blin, (float*)d_out);           // 8
}

// round 14
// speedup vs baseline: 1.3118x; 1.0730x over previous
#include <cuda_runtime.h>
#include <cuda_fp16.h>
#include <cstdint>

#define NN 100000
#define NPAD 100096   // 782*128, pad rows stay zero forever
#define NE 1600000
#define NG 1024
#define DD 128
#define NB_SCAN 391   // ceil(NN/256)

// ---------------- scratch (device globals; zero-initialized at load; k_final's
// tail re-zeros deg/cursor/alloc/pool; plane pad rows are never written) -------
__device__ __half g_xH[NPAD * DD];
__device__ __half g_xL[NPAD * DD];
__device__ __half g_hH[NPAD * DD];   // h1 hi plane (gemm2 A)
__device__ __half g_hL[NPAD * DD];
__device__ __half g_yB[NPAD * DD];   // Y = src@Wl^T, fp16 (gather source)
__device__ float g_z[NN * DD];       // Z = src@Wr^T, fp32
__device__ float g_h2[NN * DD];
__device__ float g_pool[NG * DD];
// W frags fp16 (no split): [layer][j 0..31][s 0..7][lane] -> uint2 {h01, h23}
__device__ uint2 g_Wf[2 * 32 * 8 * 32];
__device__ int   g_deg[NN];
__device__ int   g_rowptr[NN];
__device__ int   g_cursor[NN];
__device__ int   g_esrc[NE];
__device__ int   g_alloc;

// ---------------- helpers ----------------
__device__ __forceinline__ uint32_t smem_to_u32(const void* p) {
    uint32_t a;
    asm("{ .reg .u64 t; cvta.to.shared.u64 t, %1; cvt.u32.u64 %0, t; }" : "=r"(a) : "l"(p));
    return a;
}
__device__ __forceinline__ uint32_t h2u(__half2 v) { return *reinterpret_cast<uint32_t*>(&v); }

#define LDM_X4(r, addr) \
    asm volatile("ldmatrix.sync.aligned.m8n8.x4.shared.b16 {%0,%1,%2,%3}, [%4];" \
        : "=r"((r)[0]), "=r"((r)[1]), "=r"((r)[2]), "=r"((r)[3]) : "r"(addr))

#define MMA_F16(c, b0, b1, a) \
    asm volatile("mma.sync.aligned.m16n8k16.row.col.f32.f16.f16.f32 " \
        "{%0,%1,%2,%3}, {%4,%5,%6,%7}, {%8,%9}, {%0,%1,%2,%3};" \
        : "+f"((c)[0]), "+f"((c)[1]), "+f"((c)[2]), "+f"((c)[3]) \
        : "r"((a)[0]), "r"((a)[1]), "r"((a)[2]), "r"((a)[3]), "r"(b0), "r"(b1))

#define CP_ASYNC16(dst, src) \
    asm volatile("cp.async.cg.shared.global [%0], [%1], 16;" :: "r"(dst), "l"(src))
#define CP_COMMIT() asm volatile("cp.async.commit_group;" ::: "memory")
#define CP_WAIT(n)  asm volatile("cp.async.wait_group %0;" :: "n"(n) : "memory")

// ---------------- slot 0: prep (x->fp16 hi/lo planes, W fp16 frags) + degree ----
#define PREP_XB_BLKS 12500   // NN*DD/4 / 256
#define PREP_WF_BLKS 64      // 2*32*8*32 / 256
__global__ void k_prep_deg(const float* __restrict__ x,
                           const float* __restrict__ W1l, const float* __restrict__ W1r,
                           const float* __restrict__ W2l, const float* __restrict__ W2r,
                           const int* __restrict__ dst) {
    if (blockIdx.x < PREP_XB_BLKS) {
        int i = blockIdx.x * 256 + threadIdx.x;
        float4 f = ((const float4*)x)[i];
        __half2 h01 = __floats2half2_rn(f.x, f.y);
        __half2 h23 = __floats2half2_rn(f.z, f.w);
        __half2 l01 = __floats2half2_rn(f.x - __low2float(h01), f.y - __high2float(h01));
        __half2 l23 = __floats2half2_rn(f.z - __low2float(h23), f.w - __high2float(h23));
        ((uint2*)g_xH)[i] = make_uint2(h2u(h01), h2u(h23));
        ((uint2*)g_xL)[i] = make_uint2(h2u(l01), h2u(l23));
        return;
    }
    if (blockIdx.x < PREP_XB_BLKS + PREP_WF_BLKS) {
        int i = (blockIdx.x - PREP_XB_BLKS) * 256 + threadIdx.x;   // 0 .. 16383
        int lane = i & 31;
        int s = (i >> 5) & 7;         // k-step 0..7 (K=128)
        int j = (i >> 8) & 31;        // n-tile 0..31 (N=256: j<16 -> Wl, else Wr)
        int layer = i >> 13;
        int n = (j & 15) * 8 + (lane >> 2);
        int k = s * 16 + (lane & 3) * 2;
        const float* Wl = layer ? W2l : W1l;
        const float* Wr = layer ? W2r : W1r;
        const float* W = (j < 16) ? Wl : Wr;
        float w[4];
#pragma unroll
        for (int q = 0; q < 4; q++) {
            int kk = k + (q >> 1) * 8 + (q & 1);
            w[q] = W[n * DD + kk];
        }
        __half2 h01 = __floats2half2_rn(w[0], w[1]);
        __half2 h23 = __floats2half2_rn(w[2], w[3]);
        g_Wf[i] = make_uint2(h2u(h01), h2u(h23));
        return;
    }
    int i = (blockIdx.x - PREP_XB_BLKS - PREP_WF_BLKS) * 256 + threadIdx.x;
    if (i < NE) atomicAdd(&g_deg[dst[i]], 1);
}

// ---------------- slot 1: bucket allocation ----------------
__global__ void k_alloc() {
    __shared__ int s[256];
    __shared__ int base;
    int b = blockIdx.x, t = threadIdx.x;
    int i = b * 256 + t;
    int v = (i < NN) ? g_deg[i] : 0;
    s[t] = v;
    __syncthreads();
#pragma unroll
    for (int off = 1; off < 256; off <<= 1) {
        int add = (t >= off) ? s[t - off] : 0;
        __syncthreads();
        s[t] += add;
        __syncthreads();
    }
    if (t == 255) base = atomicAdd(&g_alloc, s[255]);
    __syncthreads();
    if (i < NN) g_rowptr[i] = base + s[t] - v;
}

// ---------------- slot 2: scatter edges into buckets ----------------
__global__ void k_scatter(const int* __restrict__ src, const int* __restrict__ dst) {
    int i = blockIdx.x * blockDim.x + threadIdx.x;
    if (i >= NE) return;
    int d = dst[i];
    int pos = atomicAdd(&g_cursor[d], 1);
    g_esrc[g_rowptr[d] + pos] = src[i];
}

// ---------------- slot 3 (PROFILED): GEMM  [Y|Z] = A @ [Wl;Wr]^T ----------------
// fp16 2-term split: D = Ah*W + Al*W (W single fp16). cp.async double-buffered A;
// W register-hoisted per 4 n-tiles; consecutive MMAs hit different accumulators.
#define SA_STRIDE 72
#define SA_CHUNK (128 * SA_STRIDE)                 // fp16 elems per plane-chunk
#define SMEM_GEMM (4 * SA_CHUNK * 2)               // 2 chunks x 2 planes, bytes
__global__ void __launch_bounds__(256, 2)
k_gemm(const __half* __restrict__ AH, const __half* __restrict__ AL,
       const uint2* __restrict__ Wf,
       __half* __restrict__ yB, float* __restrict__ z) {
    extern __shared__ __align__(16) __half sA[];   // [chunk][plane][SA_CHUNK]
    int tid = threadIdx.x;
    int wid = tid >> 5, lane = tid & 31;
    int m0 = blockIdx.x * 128;
    int wm = wid & 3, wn = wid >> 2;
    int jbase = blockIdx.y * 16;

    float acc[2][8][4];
#pragma unroll
    for (int a = 0; a < 2; a++)
#pragma unroll
        for (int b = 0; b < 8; b++)
#pragma unroll
            for (int q = 0; q < 4; q++) acc[a][b][q] = 0.f;

    int frow = tid >> 1, fhalf = tid & 1;   // plane pad rows are zero -> no guard
    int g = lane >> 3, ri = lane & 7;
    uint32_t sbase = smem_to_u32(sA);

    // ---- issue both chunks' async copies up front ----
#pragma unroll
    for (int c = 0; c < 2; c++) {
#pragma unroll
        for (int p = 0; p < 2; p++) {
            const __half* gsrc =
                (p ? AL : AH) + (size_t)(m0 + frow) * DD + c * 64 + fhalf * 32;
            uint32_t sdst = sbase + (uint32_t)((c * 2 + p) * SA_CHUNK
                                               + frow * SA_STRIDE + fhalf * 32) * 2;
#pragma unroll
            for (int q = 0; q < 4; q++)
                CP_ASYNC16(sdst + q * 16, (const char*)(gsrc + q * 8));
        }
        CP_COMMIT();
    }

#pragma unroll 1
    for (int c = 0; c < 2; c++) {
        if (c == 0) CP_WAIT(1); else CP_WAIT(0);
        __syncthreads();
        uint32_t sAh_u = sbase + (uint32_t)(c * 2 + 0) * SA_CHUNK * 2;
        uint32_t sAl_u = sbase + (uint32_t)(c * 2 + 1) * SA_CHUNK * 2;

#pragma unroll
        for (int ss = 0; ss < 4; ss++) {
            int s = c * 4 + ss;
            int k0 = ss * 16;
            uint32_t Ah[2][4], Al[2][4];
#pragma unroll
            for (int mt = 0; mt < 2; mt++) {
                uint32_t row = (uint32_t)(wm * 32 + mt * 16 + (g & 1) * 8 + ri);
                uint32_t byo = (row * SA_STRIDE + (uint32_t)(k0 + (g >> 1) * 8)) * 2;
                LDM_X4(Ah[mt], sAh_u + byo);
                LDM_X4(Al[mt], sAl_u + byo);
            }
            // groups of 4 n-tiles: hoist W, 2 term-passes, 8 independent MMAs each
#pragma unroll
            for (int g4 = 0; g4 < 2; g4++) {
                uint2 wv[4];
#pragma unroll
                for (int q = 0; q < 4; q++) {
                    int j = jbase + wn * 8 + g4 * 4 + q;
                    wv[q] = __ldg(&Wf[((j * 8 + s) << 5) + lane]);
                }
                // pass 1: Ah * W
#pragma unroll
                for (int q = 0; q < 4; q++) {
                    int nt = g4 * 4 + q;
                    MMA_F16(acc[0][nt], wv[q].x, wv[q].y, Ah[0]);
                    MMA_F16(acc[1][nt], wv[q].x, wv[q].y, Ah[1]);
                }
                // pass 2: Al * W
#pragma unroll
                for (int q = 0; q < 4; q++) {
                    int nt = g4 * 4 + q;
                    MMA_F16(acc[0][nt], wv[q].x, wv[q].y, Al[0]);
                    MMA_F16(acc[1][nt], wv[q].x, wv[q].y, Al[1]);
                }
            }
        }
    }

    // epilogue: y-half (blockIdx.y==0) -> fp16, z-half -> fp32; no bias
    int r_in = lane >> 2;
    int n_in = (lane & 3) * 2;
    bool isY = (blockIdx.y == 0);
#pragma unroll
    for (int nt = 0; nt < 8; nt++) {
        int n = wn * 64 + nt * 8 + n_in;   // 0..127 within half
#pragma unroll
        for (int mt = 0; mt < 2; mt++) {
            int r0 = m0 + wm * 32 + mt * 16 + r_in;
            if (r0 < NN) {
                if (isY) {
                    __half2 o = __floats2half2_rn(acc[mt][nt][0], acc[mt][nt][1]);
                    *(uint32_t*)(yB + (size_t)r0 * DD + n) = h2u(o);
                } else {
                    *(float2*)(z + (size_t)r0 * DD + n) = make_float2(acc[mt][nt][0], acc[mt][nt][1]);
                }
            }
            int r1 = r0 + 8;
            if (r1 < NN) {
                if (isY) {
                    __half2 o = __floats2half2_rn(acc[mt][nt][2], acc[mt][nt][3]);
                    *(uint32_t*)(yB + (size_t)r1 * DD + n) = h2u(o);
                } else {
                    *(float2*)(z + (size_t)r1 * DD + n) = make_float2(acc[mt][nt][2], acc[mt][nt][3]);
                }
            }
        }
    }
}

// ---------------- fused agg + epilogue: h = relu(mean_nb(Y) + Z + bias) ----------
__global__ void k_aggf(const float* __restrict__ z, const float* __restrict__ bias,
                       __half* __restrict__ outH, __half* __restrict__ outL,
                       float* __restrict__ outF) {
    int w = (blockIdx.x * blockDim.x + threadIdx.x) >> 5;
    int lane = threadIdx.x & 31;
    if (w >= NN) return;
    int beg = g_rowptr[w];
    int dcnt = g_deg[w];
    int end = beg + dcnt;
    const uint2* in2 = (const uint2*)g_yB;
    float a0 = 0.f, a1 = 0.f, a2 = 0.f, a3 = 0.f;
    int e = beg;
#pragma unroll 1
    for (; e + 7 < end; e += 8) {
        int s0 = __ldg(&g_esrc[e]);
        int s1 = __ldg(&g_esrc[e + 1]);
        int s2 = __ldg(&g_esrc[e + 2]);
        int s3 = __ldg(&g_esrc[e + 3]);
        int s4 = __ldg(&g_esrc[e + 4]);
        int s5 = __ldg(&g_esrc[e + 5]);
        int s6 = __ldg(&g_esrc[e + 6]);
        int s7 = __ldg(&g_esrc[e + 7]);
        uint2 v0 = __ldg(&in2[(size_t)s0 * 32 + lane]);
        uint2 v1 = __ldg(&in2[(size_t)s1 * 32 + lane]);
        uint2 v2 = __ldg(&in2[(size_t)s2 * 32 + lane]);
        uint2 v3 = __ldg(&in2[(size_t)s3 * 32 + lane]);
        uint2 v4 = __ldg(&in2[(size_t)s4 * 32 + lane]);
        uint2 v5 = __ldg(&in2[(size_t)s5 * 32 + lane]);
        uint2 v6 = __ldg(&in2[(size_t)s6 * 32 + lane]);
        uint2 v7 = __ldg(&in2[(size_t)s7 * 32 + lane]);
#pragma unroll
        for (int q = 0; q < 8; q++) {
            uint2 v = q == 0 ? v0 : q == 1 ? v1 : q == 2 ? v2 : q == 3 ? v3
                    : q == 4 ? v4 : q == 5 ? v5 : q == 6 ? v6 : v7;
            float2 p0 = __half22float2(*(__half2*)&v.x);
            float2 p1 = __half22float2(*(__half2*)&v.y);
            a0 += p0.x; a1 += p0.y; a2 += p1.x; a3 += p1.y;
        }
    }
    for (; e < end; e++) {
        int s0 = __ldg(&g_esrc[e]);
        uint2 v = __ldg(&in2[(size_t)s0 * 32 + lane]);
        float2 p0 = __half22float2(*(__half2*)&v.x);
        float2 p1 = __half22float2(*(__half2*)&v.y);
        a0 += p0.x; a1 += p0.y; a2 += p1.x; a3 += p1.y;
    }
    float inv = (dcnt > 0) ? 1.0f / (float)dcnt : 0.0f;
    float4 zz = ((const float4*)z)[w * 32 + lane];
    float4 bb = ((const float4*)bias)[lane];
    float f0 = fmaxf(a0 * inv + zz.x + bb.x, 0.f);
    float f1 = fmaxf(a1 * inv + zz.y + bb.y, 0.f);
    float f2 = fmaxf(a2 * inv + zz.z + bb.z, 0.f);
    float f3 = fmaxf(a3 * inv + zz.w + bb.w, 0.f);
    if (outF) {
        ((float4*)outF)[w * 32 + lane] = make_float4(f0, f1, f2, f3);
    } else {
        __half2 h01 = __floats2half2_rn(f0, f1);
        __half2 h23 = __floats2half2_rn(f2, f3);
        __half2 l01 = __floats2half2_rn(f0 - __low2float(h01), f1 - __high2float(h01));
        __half2 l23 = __floats2half2_rn(f2 - __low2float(h23), f3 - __high2float(h23));
        ((uint2*)outH)[w * 32 + lane] = make_uint2(h2u(h01), h2u(h23));
        ((uint2*)outL)[w * 32 + lane] = make_uint2(h2u(l01), h2u(l23));
    }
}

// ---------------- global add pool (batch is sorted, int32) ----------------
#define NPB 256
__global__ void k_pool(const float* __restrict__ h, const int* __restrict__ batch) {
    int t = threadIdx.x;
    int start = blockIdx.x * NPB;
    int end = start + NPB; if (end > NN) end = NN;
    if (start >= NN) return;
    int cur = batch[start];
    float sum = 0.f;
    for (int i = start; i < end; i++) {
        int b = __ldg(&batch[i]);
        if (b != cur) {
            atomicAdd(&g_pool[cur * DD + t], sum);
            sum = 0.f; cur = b;
        }
        sum += h[(size_t)i * DD + t];
    }
    atomicAdd(&g_pool[cur * DD + t], sum);
}

// ---------------- LayerNorm + final linear + scratch re-zero ----------------
__global__ void k_final(const float* __restrict__ ln_g, const float* __restrict__ ln_b,
                        const float* __restrict__ Wlin, const float* __restrict__ blin,
                        float* __restrict__ out) {
    int gtid = blockIdx.x * blockDim.x + threadIdx.x;
    int w = gtid >> 5;
    int lane = threadIdx.x & 31;
    if (w < NG) {
        float4 v = ((const float4*)g_pool)[w * 32 + lane];
        float s = v.x + v.y + v.z + v.w;
#pragma unroll
        for (int o = 16; o; o >>= 1) s += __shfl_xor_sync(0xffffffffu, s, o);
        float mean = s * (1.0f / 128.0f);
        float dx = v.x - mean, dy = v.y - mean, dz = v.z - mean, dw = v.w - mean;
        float q = dx * dx + dy * dy + dz * dz + dw * dw;
#pragma unroll
        for (int o = 16; o; o >>= 1) q += __shfl_xor_sync(0xffffffffu, q, o);
        float var = q * (1.0f / 128.0f);
        float r = rsqrtf(var + 1e-5f);
        float4 gg = ((const float4*)ln_g)[lane];
        float4 bb = ((const float4*)ln_b)[lane];
        float n0 = dx * r * gg.x + bb.x;
        float n1 = dy * r * gg.y + bb.y;
        float n2 = dz * r * gg.z + bb.z;
        float n3 = dw * r * gg.w + bb.w;
        float4 w0 = ((const float4*)Wlin)[lane];
        float4 w1 = ((const float4*)Wlin)[32 + lane];
        float d0 = n0 * w0.x + n1 * w0.y + n2 * w0.z + n3 * w0.w;
        float d1 = n0 * w1.x + n1 * w1.y + n2 * w1.z + n3 * w1.w;
#pragma unroll
        for (int o = 16; o; o >>= 1) {
            d0 += __shfl_xor_sync(0xffffffffu, d0, o);
            d1 += __shfl_xor_sync(0xffffffffu, d1, o);
        }
        if (lane == 0) {
            out[w * 2 + 0] = d0 + blin[0];
            out[w * 2 + 1] = d1 + blin[1];
        }
        ((float4*)g_pool)[w * 32 + lane] = make_float4(0.f, 0.f, 0.f, 0.f);
    }
    if (gtid == 0) g_alloc = 0;
    for (int i = gtid; i < NN; i += NG * 32) { g_deg[i] = 0; g_cursor[i] = 0; }
}

// ---------------- launch ----------------
extern "C" void kernel_launch(void* const* d_in, const int* in_sizes, int n_in,
                              void* d_out, int out_size) {
    const float* x     = (const float*)d_in[0];
    const int*   ei    = (const int*)d_in[1];
    const int*   bat   = (const int*)d_in[2];
    const float* W1l   = (const float*)d_in[3];
    const float* b1l   = (const float*)d_in[4];
    const float* W1r   = (const float*)d_in[5];
    const float* W2l   = (const float*)d_in[6];
    const float* b2l   = (const float*)d_in[7];
    const float* W2r   = (const float*)d_in[8];
    const float* ln_g  = (const float*)d_in[9];
    const float* ln_b  = (const float*)d_in[10];
    const float* Wlin  = (const float*)d_in[11];
    const float* blin  = (const float*)d_in[12];

    const int* src = ei;
    const int* dst = ei + NE;

    __half *xH, *xL, *hH, *hL, *yB;
    float *z, *h2;
    uint2* wf;
    cudaGetSymbolAddress((void**)&xH, g_xH);
    cudaGetSymbolAddress((void**)&xL, g_xL);
    cudaGetSymbolAddress((void**)&hH, g_hH);
    cudaGetSymbolAddress((void**)&hL, g_hL);
    cudaGetSymbolAddress((void**)&yB, g_yB);
    cudaGetSymbolAddress((void**)&z,  g_z);
    cudaGetSymbolAddress((void**)&h2, g_h2);
    cudaGetSymbolAddress((void**)&wf, g_Wf);

    cudaFuncSetAttribute(k_gemm, cudaFuncAttributeMaxDynamicSharedMemorySize, SMEM_GEMM);

    int degblks = (NE + 255) / 256;
    k_prep_deg<<<PREP_XB_BLKS + PREP_WF_BLKS + degblks, 256>>>(x, W1l, W1r, W2l, W2r, dst);  // 0
    k_alloc<<<NB_SCAN, 256>>>();                                                              // 1
    k_scatter<<<degblks, 256>>>(src, dst);                                                    // 2

    const int LSTRIDE = 32 * 8 * 32;   // uint2 per layer
    dim3 ggrid((NN + 127) / 128, 2);
    k_gemm<<<ggrid, 256, SMEM_GEMM>>>(xH, xL, wf, yB, z);                                     // 3 (profiled)
    k_aggf<<<(NN * 32 + 255) / 256, 256>>>(z, b1l, hH, hL, (float*)nullptr);                  // 4
    k_gemm<<<ggrid, 256, SMEM_GEMM>>>(hH, hL, wf + LSTRIDE, yB, z);                           // 5
    k_aggf<<<(NN * 32 + 255) / 256, 256>>>(z, b2l, (__half*)nullptr,
                                           (__half*)nullptr, h2);                             // 6

    k_pool<<<(NN + NPB - 1) / NPB, 128>>>(h2, bat);                                           // 7
    k_final<<<(NG * 32 + 255) / 256, 256>>>(ln_g, ln_b, Wlin, blin, (float*)d_out);           // 8
}

// round 15
// speedup vs baseline: 1.3216x; 1.0075x over previous
#include <cuda_runtime.h>
#include <cuda_fp16.h>
#include <cstdint>

#define NN 100000
#define NPAD 100096   // 782*128, pad rows stay zero forever
#define NE 1600000
#define NG 1024
#define DD 128
#define NB_SCAN 391   // ceil(NN/256)

// ---------------- scratch (device globals; zero-initialized at load; k_final's
// tail re-zeros deg/cursor/alloc/pool; plane pad rows are never written) -------
__device__ __half g_xH[NPAD * DD];
__device__ __half g_xL[NPAD * DD];
__device__ __half g_hH[NPAD * DD];   // h1 hi plane (gemm2 A)
__device__ __half g_hL[NPAD * DD];
__device__ __half g_yB[NPAD * DD];   // Y = src@Wl^T, fp16 (gather source)
__device__ float g_z[NN * DD];       // Z = src@Wr^T, fp32
__device__ float g_h2[NN * DD];
__device__ float g_pool[NG * DD];
// W frags fp16: [layer][j 0..31][s 0..7][lane] -> uint2 {h01, h23}
__device__ uint2 g_Wf[2 * 32 * 8 * 32];
__device__ int   g_deg[NN];
__device__ int   g_rowptr[NN];
__device__ int   g_cursor[NN];
__device__ int   g_esrc[NE];
__device__ int   g_alloc;

// ---------------- helpers ----------------
__device__ __forceinline__ uint32_t smem_to_u32(const void* p) {
    uint32_t a;
    asm("{ .reg .u64 t; cvta.to.shared.u64 t, %1; cvt.u32.u64 %0, t; }" : "=r"(a) : "l"(p));
    return a;
}
__device__ __forceinline__ uint32_t h2u(__half2 v) { return *reinterpret_cast<uint32_t*>(&v); }

#define LDM_X4(r, addr) \
    asm volatile("ldmatrix.sync.aligned.m8n8.x4.shared.b16 {%0,%1,%2,%3}, [%4];" \
        : "=r"((r)[0]), "=r"((r)[1]), "=r"((r)[2]), "=r"((r)[3]) : "r"(addr))

#define MMA_F16(c, b0, b1, a) \
    asm volatile("mma.sync.aligned.m16n8k16.row.col.f32.f16.f16.f32 " \
        "{%0,%1,%2,%3}, {%4,%5,%6,%7}, {%8,%9}, {%0,%1,%2,%3};" \
        : "+f"((c)[0]), "+f"((c)[1]), "+f"((c)[2]), "+f"((c)[3]) \
        : "r"((a)[0]), "r"((a)[1]), "r"((a)[2]), "r"((a)[3]), "r"(b0), "r"(b1))

#define CP_ASYNC16(dst, src) \
    asm volatile("cp.async.cg.shared.global [%0], [%1], 16;" :: "r"(dst), "l"(src))
#define CP_COMMIT() asm volatile("cp.async.commit_group;" ::: "memory")
#define CP_WAIT(n)  asm volatile("cp.async.wait_group %0;" :: "n"(n) : "memory")

// ---------------- slot 0: prep (x->fp16 hi/lo planes, W fp16 frags) + degree ----
#define PREP_XB_BLKS 12500   // NN*DD/4 / 256
#define PREP_WF_BLKS 64      // 2*32*8*32 / 256
__global__ void k_prep_deg(const float* __restrict__ x,
                           const float* __restrict__ W1l, const float* __restrict__ W1r,
                           const float* __restrict__ W2l, const float* __restrict__ W2r,
                           const int* __restrict__ dst) {
    if (blockIdx.x < PREP_XB_BLKS) {
        int i = blockIdx.x * 256 + threadIdx.x;
        float4 f = ((const float4*)x)[i];
        __half2 h01 = __floats2half2_rn(f.x, f.y);
        __half2 h23 = __floats2half2_rn(f.z, f.w);
        __half2 l01 = __floats2half2_rn(f.x - __low2float(h01), f.y - __high2float(h01));
        __half2 l23 = __floats2half2_rn(f.z - __low2float(h23), f.w - __high2float(h23));
        ((uint2*)g_xH)[i] = make_uint2(h2u(h01), h2u(h23));
        ((uint2*)g_xL)[i] = make_uint2(h2u(l01), h2u(l23));
        return;
    }
    if (blockIdx.x < PREP_XB_BLKS + PREP_WF_BLKS) {
        int i = (blockIdx.x - PREP_XB_BLKS) * 256 + threadIdx.x;   // 0 .. 16383
        int lane = i & 31;
        int s = (i >> 5) & 7;         // k-step 0..7 (K=128)
        int j = (i >> 8) & 31;        // n-tile 0..31 (N=256: j<16 -> Wl, else Wr)
        int layer = i >> 13;
        int n = (j & 15) * 8 + (lane >> 2);
        int k = s * 16 + (lane & 3) * 2;
        const float* Wl = layer ? W2l : W1l;
        const float* Wr = layer ? W2r : W1r;
        const float* W = (j < 16) ? Wl : Wr;
        float w[4];
#pragma unroll
        for (int q = 0; q < 4; q++) {
            int kk = k + (q >> 1) * 8 + (q & 1);
            w[q] = W[n * DD + kk];
        }
        __half2 h01 = __floats2half2_rn(w[0], w[1]);
        __half2 h23 = __floats2half2_rn(w[2], w[3]);
        g_Wf[i] = make_uint2(h2u(h01), h2u(h23));
        return;
    }
    int i = (blockIdx.x - PREP_XB_BLKS - PREP_WF_BLKS) * 256 + threadIdx.x;
    if (i < NE) atomicAdd(&g_deg[dst[i]], 1);
}

// ---------------- slot 1: bucket allocation ----------------
__global__ void k_alloc() {
    __shared__ int s[256];
    __shared__ int base;
    int b = blockIdx.x, t = threadIdx.x;
    int i = b * 256 + t;
    int v = (i < NN) ? g_deg[i] : 0;
    s[t] = v;
    __syncthreads();
#pragma unroll
    for (int off = 1; off < 256; off <<= 1) {
        int add = (t >= off) ? s[t - off] : 0;
        __syncthreads();
        s[t] += add;
        __syncthreads();
    }
    if (t == 255) base = atomicAdd(&g_alloc, s[255]);
    __syncthreads();
    if (i < NN) g_rowptr[i] = base + s[t] - v;
}

// ---------------- slot 2: scatter edges into buckets ----------------
__global__ void k_scatter(const int* __restrict__ src, const int* __restrict__ dst) {
    int i = blockIdx.x * blockDim.x + threadIdx.x;
    if (i >= NE) return;
    int d = dst[i];
    int pos = atomicAdd(&g_cursor[d], 1);
    g_esrc[g_rowptr[d] + pos] = src[i];
}

// ---------------- slot 3 (PROFILED): GEMM  [Y|Z] = A @ [Wl;Wr]^T ----------------
// fp16 2-term split. A double-buffered via cp.async; block's 32KB W half staged
// in SMEM once (cp.async, overlapped with A chunk-0) -> inner W reads are 29cyc
// LDS.64 instead of 234cyc L2 LDG.
#define SA_STRIDE 72
#define SA_CHUNK (128 * SA_STRIDE)                 // fp16 elems per plane-chunk
#define SW_OFF   (4 * SA_CHUNK * 2)                // byte offset of W region
#define SW_BYTES (16 * 8 * 32 * 8)                 // 32KB: 16 j-tiles x 8 s x 32 lanes x uint2
#define SMEM_GEMM (SW_OFF + SW_BYTES)
__global__ void __launch_bounds__(256, 2)
k_gemm(const __half* __restrict__ AH, const __half* __restrict__ AL,
       const uint2* __restrict__ Wf,
       __half* __restrict__ yB, float* __restrict__ z) {
    extern __shared__ __align__(16) __half sA[];   // [chunk][plane][SA_CHUNK] then W
    int tid = threadIdx.x;
    int wid = tid >> 5, lane = tid & 31;
    int m0 = blockIdx.x * 128;
    int wm = wid & 3, wn = wid >> 2;
    int jbase = blockIdx.y * 16;

    float acc[2][8][4];
#pragma unroll
    for (int a = 0; a < 2; a++)
#pragma unroll
        for (int b = 0; b < 8; b++)
#pragma unroll
            for (int q = 0; q < 4; q++) acc[a][b][q] = 0.f;

    int frow = tid >> 1, fhalf = tid & 1;   // plane pad rows are zero -> no guard
    int g = lane >> 3, ri = lane & 7;
    uint32_t sbase = smem_to_u32(sA);
    uint32_t swbase = sbase + SW_OFF;

    // ---- group 0: W half (32KB contiguous from Wf + jbase*256) + A chunk 0 ----
    {
        const char* wsrc = (const char*)(Wf + jbase * 256);
#pragma unroll
        for (int q = 0; q < 8; q++) {
            uint32_t off = (uint32_t)(tid * 16 + q * 4096);
            CP_ASYNC16(swbase + off, wsrc + off);
        }
    }
#pragma unroll
    for (int p = 0; p < 2; p++) {
        const __half* gsrc = (p ? AL : AH) + (size_t)(m0 + frow) * DD + fhalf * 32;
        uint32_t sdst = sbase + (uint32_t)(p * SA_CHUNK + frow * SA_STRIDE + fhalf * 32) * 2;
#pragma unroll
        for (int q = 0; q < 4; q++)
            CP_ASYNC16(sdst + q * 16, (const char*)(gsrc + q * 8));
    }
    CP_COMMIT();
    // ---- group 1: A chunk 1 ----
#pragma unroll
    for (int p = 0; p < 2; p++) {
        const __half* gsrc = (p ? AL : AH) + (size_t)(m0 + frow) * DD + 64 + fhalf * 32;
        uint32_t sdst = sbase + (uint32_t)((2 + p) * SA_CHUNK + frow * SA_STRIDE + fhalf * 32) * 2;
#pragma unroll
        for (int q = 0; q < 4; q++)
            CP_ASYNC16(sdst + q * 16, (const char*)(gsrc + q * 8));
    }
    CP_COMMIT();

#pragma unroll 1
    for (int c = 0; c < 2; c++) {
        if (c == 0) CP_WAIT(1); else CP_WAIT(0);
        __syncthreads();
        uint32_t sAh_u = sbase + (uint32_t)(c * 2 + 0) * SA_CHUNK * 2;
        uint32_t sAl_u = sbase + (uint32_t)(c * 2 + 1) * SA_CHUNK * 2;

#pragma unroll
        for (int ss = 0; ss < 4; ss++) {
            int s = c * 4 + ss;
            int k0 = ss * 16;
            uint32_t Ah[2][4], Al[2][4];
#pragma unroll
            for (int mt = 0; mt < 2; mt++) {
                uint32_t row = (uint32_t)(wm * 32 + mt * 16 + (g & 1) * 8 + ri);
                uint32_t byo = (row * SA_STRIDE + (uint32_t)(k0 + (g >> 1) * 8)) * 2;
                LDM_X4(Ah[mt], sAh_u + byo);
                LDM_X4(Al[mt], sAl_u + byo);
            }
            // groups of 4 n-tiles: W from SMEM (LDS.64), 2 term-passes
#pragma unroll
            for (int g4 = 0; g4 < 2; g4++) {
                uint2 wv[4];
#pragma unroll
                for (int q = 0; q < 4; q++) {
                    int jj = wn * 8 + g4 * 4 + q;   // 0..15 within half
                    uint32_t off = (uint32_t)(((jj * 8 + s) << 5) + lane) * 8;
                    asm volatile("ld.shared.v2.u32 {%0,%1}, [%2];"
                        : "=r"(wv[q].x), "=r"(wv[q].y) : "r"(swbase + off));
                }
                // pass 1: Ah * W
#pragma unroll
                for (int q = 0; q < 4; q++) {
                    int nt = g4 * 4 + q;
                    MMA_F16(acc[0][nt], wv[q].x, wv[q].y, Ah[0]);
                    MMA_F16(acc[1][nt], wv[q].x, wv[q].y, Ah[1]);
                }
                // pass 2: Al * W
#pragma unroll
                for (int q = 0; q < 4; q++) {
                    int nt = g4 * 4 + q;
                    MMA_F16(acc[0][nt], wv[q].x, wv[q].y, Al[0]);
                    MMA_F16(acc[1][nt], wv[q].x, wv[q].y, Al[1]);
                }
            }
        }
    }

    // epilogue: y-half (blockIdx.y==0) -> fp16, z-half -> fp32; no bias
    int r_in = lane >> 2;
    int n_in = (lane & 3) * 2;
    bool isY = (blockIdx.y == 0);
#pragma unroll
    for (int nt = 0; nt < 8; nt++) {
        int n = wn * 64 + nt * 8 + n_in;   // 0..127 within half
#pragma unroll
        for (int mt = 0; mt < 2; mt++) {
            int r0 = m0 + wm * 32 + mt * 16 + r_in;
            if (r0 < NN) {
                if (isY) {
                    __half2 o = __floats2half2_rn(acc[mt][nt][0], acc[mt][nt][1]);
                    *(uint32_t*)(yB + (size_t)r0 * DD + n) = h2u(o);
                } else {
                    *(float2*)(z + (size_t)r0 * DD + n) = make_float2(acc[mt][nt][0], acc[mt][nt][1]);
                }
            }
            int r1 = r0 + 8;
            if (r1 < NN) {
                if (isY) {
                    __half2 o = __floats2half2_rn(acc[mt][nt][2], acc[mt][nt][3]);
                    *(uint32_t*)(yB + (size_t)r1 * DD + n) = h2u(o);
                } else {
                    *(float2*)(z + (size_t)r1 * DD + n) = make_float2(acc[mt][nt][2], acc[mt][nt][3]);
                }
            }
        }
    }
}

// ---------------- fused agg + epilogue: h = relu(mean_nb(Y) + Z + bias) ----------
__global__ void k_aggf(const float* __restrict__ z, const float* __restrict__ bias,
                       __half* __restrict__ outH, __half* __restrict__ outL,
                       float* __restrict__ outF) {
    int w = (blockIdx.x * blockDim.x + threadIdx.x) >> 5;
    int lane = threadIdx.x & 31;
    if (w >= NN) return;
    int beg = g_rowptr[w];
    int dcnt = g_deg[w];
    int end = beg + dcnt;
    const uint2* in2 = (const uint2*)g_yB;
    float a0 = 0.f, a1 = 0.f, a2 = 0.f, a3 = 0.f;
    int e = beg;
#pragma unroll 1
    for (; e + 7 < end; e += 8) {
        int s0 = __ldg(&g_esrc[e]);
        int s1 = __ldg(&g_esrc[e + 1]);
        int s2 = __ldg(&g_esrc[e + 2]);
        int s3 = __ldg(&g_esrc[e + 3]);
        int s4 = __ldg(&g_esrc[e + 4]);
        int s5 = __ldg(&g_esrc[e + 5]);
        int s6 = __ldg(&g_esrc[e + 6]);
        int s7 = __ldg(&g_esrc[e + 7]);
        uint2 v0 = __ldg(&in2[(size_t)s0 * 32 + lane]);
        uint2 v1 = __ldg(&in2[(size_t)s1 * 32 + lane]);
        uint2 v2 = __ldg(&in2[(size_t)s2 * 32 + lane]);
        uint2 v3 = __ldg(&in2[(size_t)s3 * 32 + lane]);
        uint2 v4 = __ldg(&in2[(size_t)s4 * 32 + lane]);
        uint2 v5 = __ldg(&in2[(size_t)s5 * 32 + lane]);
        uint2 v6 = __ldg(&in2[(size_t)s6 * 32 + lane]);
        uint2 v7 = __ldg(&in2[(size_t)s7 * 32 + lane]);
#pragma unroll
        for (int q = 0; q < 8; q++) {
            uint2 v = q == 0 ? v0 : q == 1 ? v1 : q == 2 ? v2 : q == 3 ? v3
                    : q == 4 ? v4 : q == 5 ? v5 : q == 6 ? v6 : v7;
            float2 p0 = __half22float2(*(__half2*)&v.x);
            float2 p1 = __half22float2(*(__half2*)&v.y);
            a0 += p0.x; a1 += p0.y; a2 += p1.x; a3 += p1.y;
        }
    }
    for (; e < end; e++) {
        int s0 = __ldg(&g_esrc[e]);
        uint2 v = __ldg(&in2[(size_t)s0 * 32 + lane]);
        float2 p0 = __half22float2(*(__half2*)&v.x);
        float2 p1 = __half22float2(*(__half2*)&v.y);
        a0 += p0.x; a1 += p0.y; a2 += p1.x; a3 += p1.y;
    }
    float inv = (dcnt > 0) ? 1.0f / (float)dcnt : 0.0f;
    float4 zz = ((const float4*)z)[w * 32 + lane];
    float4 bb = ((const float4*)bias)[lane];
    float f0 = fmaxf(a0 * inv + zz.x + bb.x, 0.f);
    float f1 = fmaxf(a1 * inv + zz.y + bb.y, 0.f);
    float f2 = fmaxf(a2 * inv + zz.z + bb.z, 0.f);
    float f3 = fmaxf(a3 * inv + zz.w + bb.w, 0.f);
    if (outF) {
        ((float4*)outF)[w * 32 + lane] = make_float4(f0, f1, f2, f3);
    } else {
        __half2 h01 = __floats2half2_rn(f0, f1);
        __half2 h23 = __floats2half2_rn(f2, f3);
        __half2 l01 = __floats2half2_rn(f0 - __low2float(h01), f1 - __high2float(h01));
        __half2 l23 = __floats2half2_rn(f2 - __low2float(h23), f3 - __high2float(h23));
        ((uint2*)outH)[w * 32 + lane] = make_uint2(h2u(h01), h2u(h23));
        ((uint2*)outL)[w * 32 + lane] = make_uint2(h2u(l01), h2u(l23));
    }
}

// ---------------- global add pool (batch is sorted, int32) ----------------
#define NPB 256
__global__ void k_pool(const float* __restrict__ h, const int* __restrict__ batch) {
    int t = threadIdx.x;
    int start = blockIdx.x * NPB;
    int end = start + NPB; if (end > NN) end = NN;
    if (start >= NN) return;
    int cur = batch[start];
    float sum = 0.f;
    for (int i = start; i < end; i++) {
        int b = __ldg(&batch[i]);
        if (b != cur) {
            atomicAdd(&g_pool[cur * DD + t], sum);
            sum = 0.f; cur = b;
        }
        sum += h[(size_t)i * DD + t];
    }
    atomicAdd(&g_pool[cur * DD + t], sum);
}

// ---------------- LayerNorm + final linear + scratch re-zero ----------------
__global__ void k_final(const float* __restrict__ ln_g, const float* __restrict__ ln_b,
                        const float* __restrict__ Wlin, const float* __restrict__ blin,
                        float* __restrict__ out) {
    int gtid = blockIdx.x * blockDim.x + threadIdx.x;
    int w = gtid >> 5;
    int lane = threadIdx.x & 31;
    if (w < NG) {
        float4 v = ((const float4*)g_pool)[w * 32 + lane];
        float s = v.x + v.y + v.z + v.w;
#pragma unroll
        for (int o = 16; o; o >>= 1) s += __shfl_xor_sync(0xffffffffu, s, o);
        float mean = s * (1.0f / 128.0f);
        float dx = v.x - mean, dy = v.y - mean, dz = v.z - mean, dw = v.w - mean;
        float q = dx * dx + dy * dy + dz * dz + dw * dw;
#pragma unroll
        for (int o = 16; o; o >>= 1) q += __shfl_xor_sync(0xffffffffu, q, o);
        float var = q * (1.0f / 128.0f);
        float r = rsqrtf(var + 1e-5f);
        float4 gg = ((const float4*)ln_g)[lane];
        float4 bb = ((const float4*)ln_b)[lane];
        float n0 = dx * r * gg.x + bb.x;
        float n1 = dy * r * gg.y + bb.y;
        float n2 = dz * r * gg.z + bb.z;
        float n3 = dw * r * gg.w + bb.w;
        float4 w0 = ((const float4*)Wlin)[lane];
        float4 w1 = ((const float4*)Wlin)[32 + lane];
        float d0 = n0 * w0.x + n1 * w0.y + n2 * w0.z + n3 * w0.w;
        float d1 = n0 * w1.x + n1 * w1.y + n2 * w1.z + n3 * w1.w;
#pragma unroll
        for (int o = 16; o; o >>= 1) {
            d0 += __shfl_xor_sync(0xffffffffu, d0, o);
            d1 += __shfl_xor_sync(0xffffffffu, d1, o);
        }
        if (lane == 0) {
            out[w * 2 + 0] = d0 + blin[0];
            out[w * 2 + 1] = d1 + blin[1];
        }
        ((float4*)g_pool)[w * 32 + lane] = make_float4(0.f, 0.f, 0.f, 0.f);
    }
    if (gtid == 0) g_alloc = 0;
    for (int i = gtid; i < NN; i += NG * 32) { g_deg[i] = 0; g_cursor[i] = 0; }
}

// ---------------- launch ----------------
extern "C" void kernel_launch(void* const* d_in, const int* in_sizes, int n_in,
                              void* d_out, int out_size) {
    const float* x     = (const float*)d_in[0];
    const int*   ei    = (const int*)d_in[1];
    const int*   bat   = (const int*)d_in[2];
    const float* W1l   = (const float*)d_in[3];
    const float* b1l   = (const float*)d_in[4];
    const float* W1r   = (const float*)d_in[5];
    const float* W2l   = (const float*)d_in[6];
    const float* b2l   = (const float*)d_in[7];
    const float* W2r   = (const float*)d_in[8];
    const float* ln_g  = (const float*)d_in[9];
    const float* ln_b  = (const float*)d_in[10];
    const float* Wlin  = (const float*)d_in[11];
    const float* blin  = (const float*)d_in[12];

    const int* src = ei;
    const int* dst = ei + NE;

    __half *xH, *xL, *hH, *hL, *yB;
    float *z, *h2;
    uint2* wf;
    cudaGetSymbolAddress((void**)&xH, g_xH);
    cudaGetSymbolAddress((void**)&xL, g_xL);
    cudaGetSymbolAddress((void**)&hH, g_hH);
    cudaGetSymbolAddress((void**)&hL, g_hL);
    cudaGetSymbolAddress((void**)&yB, g_yB);
    cudaGetSymbolAddress((void**)&z,  g_z);
    cudaGetSymbolAddress((void**)&h2, g_h2);
    cudaGetSymbolAddress((void**)&wf, g_Wf);

    cudaFuncSetAttribute(k_gemm, cudaFuncAttributeMaxDynamicSharedMemorySize, SMEM_GEMM);

    int degblks = (NE + 255) / 256;
    k_prep_deg<<<PREP_XB_BLKS + PREP_WF_BLKS + degblks, 256>>>(x, W1l, W1r, W2l, W2r, dst);  // 0
    k_alloc<<<NB_SCAN, 256>>>();                                                              // 1
    k_scatter<<<degblks, 256>>>(src, dst);                                                    // 2

    const int LSTRIDE = 32 * 8 * 32;   // uint2 per layer
    dim3 ggrid((NN + 127) / 128, 2);
    k_gemm<<<ggrid, 256, SMEM_GEMM>>>(xH, xL, wf, yB, z);                                     // 3 (profiled)
    k_aggf<<<(NN * 32 + 255) / 256, 256>>>(z, b1l, hH, hL, (float*)nullptr);                  // 4
    k_gemm<<<ggrid, 256, SMEM_GEMM>>>(hH, hL, wf + LSTRIDE, yB, z);                           // 5
    k_aggf<<<(NN * 32 + 255) / 256, 256>>>(z, b2l, (__half*)nullptr,
                                           (__half*)nullptr, h2);                             // 6

    k_pool<<<(NN + NPB - 1) / NPB, 128>>>(h2, bat);                                           // 7
    k_final<<<(NG * 32 + 255) / 256, 256>>>(ln_g, ln_b, Wlin, blin, (float*)d_out);           // 8
}